// round 13
// baseline (speedup 1.0000x reference)
#include <cuda_runtime.h>
#include <cuda_fp16.h>
#include <math.h>
#include <stdint.h>

#define N_NODES 100000
#define E_MAX   3300000
#define IN_DIM  512
#define HID_DIM 512
#define OUT_DIM 64
#define HOPS    10

// ---------------- scratch (static device globals; no allocations) ----------------
__device__ __half g_h1h[(size_t)N_NODES * HID_DIM];               // 102.4 MB
__device__ __half g_Hh[(size_t)(HOPS + 1) * N_NODES * OUT_DIM];   // 140.8 MB
__device__ __half g_w1t[(size_t)HID_DIM * IN_DIM];                // 0.5 MB ([n][k])
__device__ __half g_w2t[(size_t)OUT_DIM * HID_DIM];               // 64 KB ([n][k])
__device__ int   g_deg[N_NODES];
__device__ int   g_rowptr[N_NODES + 1];
__device__ int   g_cursor[N_NODES];
__device__ int2  g_edge[E_MAX];                                   // (col, half2(w,w) bits)

// ================= PTX helpers =================
__device__ __forceinline__ uint32_t smem_u32(const void* p) {
    uint32_t a;
    asm("{ .reg .u64 t; cvta.to.shared.u64 t, %1; cvt.u32.u64 %0, t; }" : "=r"(a) : "l"(p));
    return a;
}
__device__ __forceinline__ void cp_async16(uint32_t s, const void* g, int sz) {
    asm volatile("cp.async.cg.shared.global [%0], [%1], 16, %2;"
                 :: "r"(s), "l"(g), "r"(sz) : "memory");
}
__device__ __forceinline__ void cp_commit() {
    asm volatile("cp.async.commit_group;" ::: "memory");
}
template <int N>
__device__ __forceinline__ void cp_wait() {
    asm volatile("cp.async.wait_group %0;" :: "n"(N) : "memory");
}
__device__ __forceinline__ void ldsm_x4(uint32_t* r, uint32_t addr) {
    asm volatile("ldmatrix.sync.aligned.m8n8.x4.shared.b16 {%0,%1,%2,%3}, [%4];"
                 : "=r"(r[0]), "=r"(r[1]), "=r"(r[2]), "=r"(r[3]) : "r"(addr));
}
__device__ __forceinline__ void mma_f16(float* d, const uint32_t* a, const uint32_t* b) {
    asm volatile(
        "mma.sync.aligned.m16n8k16.row.col.f32.f16.f16.f32 "
        "{%0,%1,%2,%3}, {%4,%5,%6,%7}, {%8,%9}, {%0,%1,%2,%3};"
        : "+f"(d[0]), "+f"(d[1]), "+f"(d[2]), "+f"(d[3])
        : "r"(a[0]), "r"(a[1]), "r"(a[2]), "r"(a[3]), "r"(b[0]), "r"(b[1]));
}
__device__ __forceinline__ __half2 bits2h2(int b) {
    union { int i; __half2 h; } u; u.i = b; return u.h;
}
__device__ __forceinline__ int h22bits(__half2 h) {
    union { int i; __half2 h; } u; u.h = h; return u.i;
}

// ---------------- fp16 weight conversion kernels ----------------
__global__ void conv_w1_kernel(const float* __restrict__ W1)
{
    int i = blockIdx.x * blockDim.x + threadIdx.x;  // i = n*512 + k
    if (i >= HID_DIM * IN_DIM) return;
    int n = i >> 9, k = i & 511;
    g_w1t[i] = __float2half_rn(W1[k * HID_DIM + n]);
}

__global__ void conv_w2_kernel(const float* __restrict__ W2)
{
    int i = blockIdx.x * blockDim.x + threadIdx.x;  // i = n*512 + k
    if (i >= OUT_DIM * HID_DIM) return;
    int n = i >> 9, k = i & 511;
    g_w2t[i] = __float2half_rn(W2[k * OUT_DIM + n]);
}

// ============ GEMM1 (mma.sync fp16): h1 = relu(x @ W1 + b1) -> fp16 ============
#define G1_NKC   (IN_DIM / 64)        // 8
#define G1_PA    288                  // A pitch bytes (72 words)
#define G1_PB    144                  // B pitch bytes (fp16)
#define G1_AT    (128 * G1_PA)        // 36864
#define G1_BT    (256 * G1_PB)        // 36864
#define G1_ST    (G1_AT + G1_BT)      // 73728
#define G1_SMEM  (3 * G1_ST)          // 221184

__global__ __launch_bounds__(512, 1) void gemm1_mma_kernel(
    const float* __restrict__ x, const float* __restrict__ bias, int M)
{
    extern __shared__ char smem[];
    const int tid  = threadIdx.x;
    const int wid  = tid >> 5, lane = tid & 31;
    const int wm   = wid & 3,  wn   = wid >> 2;      // 4 x 4 warps
    const int brow = blockIdx.x * 128, bcol = blockIdx.y * 256;

    const uint32_t sbase = smem_u32(smem);
    const uint32_t BOFF = G1_AT;

    float d[2][8][4];
#pragma unroll
    for (int i = 0; i < 2; i++)
#pragma unroll
        for (int j = 0; j < 8; j++)
#pragma unroll
            for (int k = 0; k < 4; k++) d[i][j][k] = 0.f;

    auto issue_load = [&](int kc, int st) {
        const int k0 = kc * 64;
        const uint32_t s0 = sbase + st * G1_ST;
#pragma unroll
        for (int i = 0; i < 4; i++) {  // A: 2048 segs of 16B (4 fp32 each)
            int seg = tid + i * 512;
            int row = seg >> 4, sc = seg & 15;
            uint32_t soff = row * G1_PA + sc * 16;
            int ar = brow + row;
            int ok = (ar < M);
            size_t gA = (size_t)(ok ? ar : 0) * IN_DIM + k0 + sc * 4;
            cp_async16(s0 + soff, x + gA, ok ? 16 : 0);
        }
#pragma unroll
        for (int i = 0; i < 4; i++) {  // B: 2048 segs (8 fp16 each)
            int seg = tid + i * 512;
            int row = seg >> 3, sc = seg & 7;
            uint32_t soff = row * G1_PB + sc * 16;
            size_t gB = (size_t)(bcol + row) * IN_DIM + k0 + sc * 8;
            cp_async16(s0 + BOFF + soff, g_w1t + gB, 16);
        }
        cp_commit();
    };

    issue_load(0, 0);
    issue_load(1, 1);

    const int g2 = lane >> 2, tq = lane & 3;

    for (int kc = 0; kc < G1_NKC; kc++) {
        if (kc == G1_NKC - 1) cp_wait<0>(); else cp_wait<1>();
        __syncthreads();
        if (kc + 2 < G1_NKC) issue_load(kc + 2, (kc + 2) % 3);

        const char*  sc8 = smem + (kc % 3) * G1_ST;
        const float* As  = (const float*)sc8;
        const uint32_t s0 = sbase + (kc % 3) * G1_ST;
#pragma unroll
        for (int ks = 0; ks < 4; ks++) {
            uint32_t a[2][4];
            const int kk = ks * 16 + tq * 2;
#pragma unroll
            for (int mt = 0; mt < 2; mt++) {
                int r0 = (wm * 32 + mt * 16 + g2) * 72;
                float2 p00 = *(const float2*)(As + r0 + kk);
                float2 p10 = *(const float2*)(As + r0 + 8 * 72 + kk);
                float2 p01 = *(const float2*)(As + r0 + kk + 8);
                float2 p11 = *(const float2*)(As + r0 + 8 * 72 + kk + 8);
                a[mt][0] = h22bits(__floats2half2_rn(p00.x, p00.y));
                a[mt][1] = h22bits(__floats2half2_rn(p10.x, p10.y));
                a[mt][2] = h22bits(__floats2half2_rn(p01.x, p01.y));
                a[mt][3] = h22bits(__floats2half2_rn(p11.x, p11.y));
            }
            const int bn_l = (lane >> 4) * 8 + (lane & 7);
            const int bk   = (ks * 16 + ((lane >> 3) & 1) * 8) * 2;
#pragma unroll
            for (int p = 0; p < 4; p++) {
                uint32_t b[4];
                int n = wn * 64 + p * 16 + bn_l;
                ldsm_x4(b, s0 + BOFF + n * G1_PB + bk);
#pragma unroll
                for (int mt = 0; mt < 2; mt++) {
#pragma unroll
                    for (int j = 0; j < 2; j++)
                        mma_f16(d[mt][2 * p + j], a[mt], b + 2 * j);
                }
            }
        }
    }

    // ---- epilogue: relu(acc + bias) -> fp16 h1
#pragma unroll
    for (int mt = 0; mt < 2; mt++) {
        int row0 = brow + wm * 32 + mt * 16 + (lane >> 2);
#pragma unroll
        for (int nt = 0; nt < 8; nt++) {
            int col = bcol + wn * 64 + nt * 8 + (lane & 3) * 2;
            float b0 = bias[col], b1 = bias[col + 1];
#pragma unroll
            for (int h = 0; h < 2; h++) {
                int r = row0 + h * 8;
                if (r >= M) continue;
                __half2 hv = __floats2half2_rn(fmaxf(d[mt][nt][2 * h + 0] + b0, 0.f),
                                               fmaxf(d[mt][nt][2 * h + 1] + b1, 0.f));
                *(__half2*)(g_h1h + (size_t)r * HID_DIM + col) = hv;
            }
        }
    }
}

// ============ GEMM2 (mma.sync fp16): H0 = h1 @ W2 + b2 -> fp16 ============
#define G2_NKC   (HID_DIM / 64)       // 8
#define G2_P     144
#define G2_AT    (128 * G2_P)         // 18432
#define G2_BT    (64 * G2_P)          // 9216
#define G2_ST    (G2_AT + G2_BT)      // 27648
#define G2_SMEM  (3 * G2_ST)          // 82944

__global__ __launch_bounds__(256, 2) void gemm2_mma_kernel(const float* __restrict__ bias, int M)
{
    extern __shared__ char smem[];
    const int tid  = threadIdx.x;
    const int wid  = tid >> 5, lane = tid & 31;
    const int wm   = wid & 3,  wn   = wid >> 2;      // 4 x 2 warps
    const int brow = blockIdx.x * 128;

    const uint32_t sbase = smem_u32(smem);
    const uint32_t AOFF = 0, BOFF = G2_AT;

    float d[2][4][4];
#pragma unroll
    for (int i = 0; i < 2; i++)
#pragma unroll
        for (int j = 0; j < 4; j++)
#pragma unroll
            for (int k = 0; k < 4; k++) d[i][j][k] = 0.f;

    auto issue_load = [&](int kc, int st) {
        const int k0 = kc * 64;
        const uint32_t s0 = sbase + st * G2_ST;
#pragma unroll
        for (int i = 0; i < 4; i++) {  // A: 1024 segs
            int seg = tid + i * 256;
            int row = seg >> 3, sc = seg & 7;
            uint32_t soff = row * G2_P + sc * 16;
            int ar = brow + row;
            int ok = (ar < M);
            size_t gA = (size_t)(ok ? ar : 0) * HID_DIM + k0 + sc * 8;
            cp_async16(s0 + AOFF + soff, g_h1h + gA, ok ? 16 : 0);
        }
#pragma unroll
        for (int i = 0; i < 2; i++) {  // B: 512 segs
            int seg = tid + i * 256;
            int row = seg >> 3, sc = seg & 7;
            uint32_t soff = row * G2_P + sc * 16;
            size_t gB = (size_t)row * HID_DIM + k0 + sc * 8;
            cp_async16(s0 + BOFF + soff, g_w2t + gB, 16);
        }
        cp_commit();
    };

    issue_load(0, 0);
    issue_load(1, 1);

    for (int kc = 0; kc < G2_NKC; kc++) {
        if (kc == G2_NKC - 1) cp_wait<0>(); else cp_wait<1>();
        __syncthreads();
        if (kc + 2 < G2_NKC) issue_load(kc + 2, (kc + 2) % 3);

        const uint32_t s0 = sbase + (kc % 3) * G2_ST;
#pragma unroll
        for (int ks = 0; ks < 4; ks++) {
            uint32_t a[2][4];
            const int ac = (ks * 16 + (lane >> 4) * 8) * 2;
#pragma unroll
            for (int mt = 0; mt < 2; mt++) {
                int r = wm * 32 + mt * 16 + (lane & 15);
                ldsm_x4(a[mt], s0 + AOFF + r * G2_P + ac);
            }
            const int bn_l = (lane >> 4) * 8 + (lane & 7);
            const int bk   = (ks * 16 + ((lane >> 3) & 1) * 8) * 2;
#pragma unroll
            for (int p = 0; p < 2; p++) {
                uint32_t b[4];
                int n = wn * 32 + p * 16 + bn_l;
                ldsm_x4(b, s0 + BOFF + n * G2_P + bk);
#pragma unroll
                for (int mt = 0; mt < 2; mt++) {
#pragma unroll
                    for (int j = 0; j < 2; j++)
                        mma_f16(d[mt][2 * p + j], a[mt], b + 2 * j);
                }
            }
        }
    }

#pragma unroll
    for (int mt = 0; mt < 2; mt++) {
        int row0 = brow + wm * 32 + mt * 16 + (lane >> 2);
#pragma unroll
        for (int nt = 0; nt < 4; nt++) {
            int col = wn * 32 + nt * 8 + (lane & 3) * 2;
            float b0 = bias[col], b1 = bias[col + 1];
#pragma unroll
            for (int h = 0; h < 2; h++) {
                int r = row0 + h * 8;
                if (r >= M) continue;
                __half2 hv = __floats2half2_rn(d[mt][nt][2 * h + 0] + b0,
                                               d[mt][nt][2 * h + 1] + b1);
                *(__half2*)(g_Hh + (size_t)r * OUT_DIM + col) = hv;
            }
        }
    }
}

// ---------------- CSR build ----------------
__global__ void zero_deg_kernel(int n)
{
    int i = blockIdx.x * blockDim.x + threadIdx.x;
    if (i < n) g_deg[i] = 0;
}

__global__ void hist_kernel(const int* __restrict__ row, int E)
{
    int e = blockIdx.x * blockDim.x + threadIdx.x;
    if (e < E) atomicAdd(&g_deg[row[e]], 1);
}

__global__ __launch_bounds__(1024) void scan_kernel(int n)
{
    __shared__ int sums[1024];
    int tid = threadIdx.x;
    int per = (n + 1023) >> 10;
    int start = tid * per;
    int end = min(start + per, n);

    int s = 0;
    for (int i = start; i < end; ++i) s += g_deg[i];
    sums[tid] = s;
    __syncthreads();

    for (int off = 1; off < 1024; off <<= 1) {
        int v = 0;
        if (tid >= off) v = sums[tid - off];
        __syncthreads();
        sums[tid] += v;
        __syncthreads();
    }

    int run = sums[tid] - s;
    for (int i = start; i < end; ++i) {
        g_rowptr[i] = run;
        g_cursor[i] = run;
        run += g_deg[i];
    }
    if (tid == 1023) g_rowptr[n] = sums[1023];
}

__global__ void scatter_kernel(const int* __restrict__ row, const int* __restrict__ col,
                               const float* __restrict__ w, int E)
{
    int e = blockIdx.x * blockDim.x + threadIdx.x;
    if (e >= E) return;
    int r = row[e];
    int pos = atomicAdd(&g_cursor[r], 1);
    __half hw = __float2half_rn(w[e]);
    __half2 w2 = __half2half2(hw);
    g_edge[pos] = make_int2(col[e], h22bits(w2));
}

// ---- shared SpMM row body: returns per-lane f[8] (sub-segment sums, all lanes) ----
__device__ __forceinline__ void spmm_row(
    const __half* __restrict__ hin, int2 (*ebuf)[32], int wslot,
    int lane, int grp, int sub, int s, int e, float* f)
{
#pragma unroll
    for (int k = 0; k < 8; k++) f[k] = 0.f;

    for (int base = s; base < e; base += 32) {
        const int cnt = min(32, e - base);
        if (lane < cnt) ebuf[wslot][lane] = g_edge[base + lane];
        __syncwarp();

        __half2 hacc[4];
#pragma unroll
        for (int k = 0; k < 4; k++) hacc[k] = __float2half2_rn(0.f);

        if (cnt == 32) {
#pragma unroll
            for (int it = 0; it < 8; ++it) {
                int2 ed = ebuf[wslot][it * 4 + grp];
                uint4 v = *(const uint4*)(hin + (size_t)ed.x * 64 + sub * 8);
                __half2 w2 = bits2h2(ed.y);
                hacc[0] = __hfma2(w2, bits2h2((int)v.x), hacc[0]);
                hacc[1] = __hfma2(w2, bits2h2((int)v.y), hacc[1]);
                hacc[2] = __hfma2(w2, bits2h2((int)v.z), hacc[2]);
                hacc[3] = __hfma2(w2, bits2h2((int)v.w), hacc[3]);
            }
        } else {
            const int nit = (cnt + 3) >> 2;
            for (int it = 0; it < nit; ++it) {
                int ei = it * 4 + grp;
                if (ei < cnt) {   // predicated: no wasted gathers
                    int2 ed = ebuf[wslot][ei];
                    uint4 v = *(const uint4*)(hin + (size_t)ed.x * 64 + sub * 8);
                    __half2 w2 = bits2h2(ed.y);
                    hacc[0] = __hfma2(w2, bits2h2((int)v.x), hacc[0]);
                    hacc[1] = __hfma2(w2, bits2h2((int)v.y), hacc[1]);
                    hacc[2] = __hfma2(w2, bits2h2((int)v.z), hacc[2]);
                    hacc[3] = __hfma2(w2, bits2h2((int)v.w), hacc[3]);
                }
            }
        }
#pragma unroll
        for (int k = 0; k < 4; k++) {
            float2 t = __half22float2(hacc[k]);
            f[2 * k]     += t.x;
            f[2 * k + 1] += t.y;
        }
        __syncwarp();
    }

    // reduce across the 4 edge groups -> all lanes hold sub-segment totals
#pragma unroll
    for (int k = 0; k < 8; k++) {
        f[k] += __shfl_xor_sync(0xffffffffu, f[k], 8);
        f[k] += __shfl_xor_sync(0xffffffffu, f[k], 16);
    }
}

// ---------------- SpMM hop (hops 1..HOPS-1) ----------------
__global__ __launch_bounds__(256) void spmm_kernel(int hop, int n)
{
    __shared__ int2 ebuf[8][32];
    const int wslot = threadIdx.x >> 5;
    const int warp  = (blockIdx.x * blockDim.x + threadIdx.x) >> 5;
    const int lane  = threadIdx.x & 31;
    if (warp >= n) return;
    const int grp = lane >> 3;
    const int sub = lane & 7;

    const __half* __restrict__ hin = g_Hh + (size_t)(hop - 1) * N_NODES * OUT_DIM;
    __half* __restrict__ hout      = g_Hh + (size_t)hop * N_NODES * OUT_DIM;

    float f[8];
    spmm_row(hin, ebuf, wslot, lane, grp, sub, g_rowptr[warp], g_rowptr[warp + 1], f);

    if (grp == 0) {
        union { __half2 h[4]; uint4 u; } o;
#pragma unroll
        for (int k = 0; k < 4; k++)
            o.h[k] = __floats2half2_rn(f[2 * k], f[2 * k + 1]);
        *(uint4*)(hout + (size_t)warp * 64 + sub * 8) = o.u;
    }
}

// ------- Final hop fused with combine: hop-10 value stays in registers -------
// UNIFORM 3-iteration loop over stored hops (k = kk*4 + grp, predicated) so every
// __shfl_xor_sync executes warp-converged.
__global__ __launch_bounds__(256) void spmm_combine_kernel(
    const float* __restrict__ s, float* __restrict__ out, int n)
{
    __shared__ int2 ebuf[8][32];
    const int wslot = threadIdx.x >> 5;
    const int warp  = (blockIdx.x * blockDim.x + threadIdx.x) >> 5;
    const int lane  = threadIdx.x & 31;
    if (warp >= n) return;
    const int grp = lane >> 3;
    const int sub = lane & 7;

    const __half* __restrict__ hin = g_Hh + (size_t)(HOPS - 1) * N_NODES * OUT_DIM;

    float f[8];
    spmm_row(hin, ebuf, wslot, lane, grp, sub, g_rowptr[warp], g_rowptr[warp + 1], f);

    float sv[8];
    *(float4*)(sv)     = *(const float4*)(s + sub * 8);
    *(float4*)(sv + 4) = *(const float4*)(s + sub * 8 + 4);

    // hop-10 gate from in-register values (uniform across warp)
    float d10 = 0.f;
#pragma unroll
    for (int j = 0; j < 8; j++) d10 += f[j] * sv[j];
    d10 += __shfl_xor_sync(0xffffffffu, d10, 1);
    d10 += __shfl_xor_sync(0xffffffffu, d10, 2);
    d10 += __shfl_xor_sync(0xffffffffu, d10, 4);
    float sg10 = 1.f / (1.f + expf(-d10));

    float acc[8];
#pragma unroll
    for (int j = 0; j < 8; j++) acc[j] = (grp == 0) ? sg10 * f[j] : 0.f;

    // stored hops 0..9: uniform trip count; group g handles k = kk*4 + g (pred k<HOPS)
#pragma unroll
    for (int kk = 0; kk < 3; kk++) {
        int k = kk * 4 + grp;
        bool act = (k < HOPS);
        uint4 v = make_uint4(0, 0, 0, 0);
        if (act) {
            const __half* hk = g_Hh + (size_t)k * N_NODES * OUT_DIM
                             + (size_t)warp * 64 + sub * 8;
            v = *(const uint4*)hk;
        }
        float2 f0 = __half22float2(bits2h2((int)v.x));
        float2 f1 = __half22float2(bits2h2((int)v.y));
        float2 f2 = __half22float2(bits2h2((int)v.z));
        float2 f3 = __half22float2(bits2h2((int)v.w));
        float fv[8] = {f0.x, f0.y, f1.x, f1.y, f2.x, f2.y, f3.x, f3.y};

        float d = 0.f;
#pragma unroll
        for (int j = 0; j < 8; j++) d += fv[j] * sv[j];
        d += __shfl_xor_sync(0xffffffffu, d, 1);   // converged: all lanes, all iters
        d += __shfl_xor_sync(0xffffffffu, d, 2);
        d += __shfl_xor_sync(0xffffffffu, d, 4);
        float sg = 1.f / (1.f + expf(-d));
        if (act) {
#pragma unroll
            for (int j = 0; j < 8; j++) acc[j] += sg * fv[j];
        }
    }

    // sum group contributions
#pragma unroll
    for (int j = 0; j < 8; j++) {
        acc[j] += __shfl_xor_sync(0xffffffffu, acc[j], 8);
        acc[j] += __shfl_xor_sync(0xffffffffu, acc[j], 16);
    }
    if (grp == 0) {
        float* dst = out + (size_t)warp * 64 + sub * 8;
        *(float4*)(dst)     = *(float4*)(acc);
        *(float4*)(dst + 4) = *(float4*)(acc + 4);
    }
}

// ---------------- launch ----------------
extern "C" void kernel_launch(void* const* d_in, const int* in_sizes, int n_in,
                              void* d_out, int out_size)
{
    const float* x   = (const float*)d_in[0];
    const int*   row = (const int*)  d_in[1];
    const int*   col = (const int*)  d_in[2];
    const float* ew  = (const float*)d_in[3];
    const float* W1  = (const float*)d_in[4];
    const float* b1  = (const float*)d_in[5];
    const float* W2  = (const float*)d_in[6];
    const float* b2  = (const float*)d_in[7];
    const float* s   = (const float*)d_in[8];

    int M = in_sizes[0] / IN_DIM;  // 100000
    int E = in_sizes[1];           // 3300000

    static bool attr_set = false;
    static cudaStream_t s_csr = 0;
    static cudaEvent_t ev_fork = 0, ev_join = 0;
    if (!attr_set) {
        cudaFuncSetAttribute(gemm1_mma_kernel,
                             cudaFuncAttributeMaxDynamicSharedMemorySize, G1_SMEM);
        cudaFuncSetAttribute(gemm2_mma_kernel,
                             cudaFuncAttributeMaxDynamicSharedMemorySize, G2_SMEM);
        cudaStreamCreateWithFlags(&s_csr, cudaStreamNonBlocking);
        cudaEventCreateWithFlags(&ev_fork, cudaEventDisableTiming);
        cudaEventCreateWithFlags(&ev_join, cudaEventDisableTiming);
        attr_set = true;
    }

    // ---- fork: CSR build runs concurrently with conversions + GEMMs ----
    cudaEventRecord(ev_fork, 0);
    cudaStreamWaitEvent(s_csr, ev_fork, 0);
    zero_deg_kernel<<<(M + 255) / 256, 256, 0, s_csr>>>(M);
    hist_kernel<<<(E + 255) / 256, 256, 0, s_csr>>>(row, E);
    scan_kernel<<<1, 1024, 0, s_csr>>>(M);
    scatter_kernel<<<(E + 255) / 256, 256, 0, s_csr>>>(row, col, ew, E);
    cudaEventRecord(ev_join, s_csr);

    // main stream: weight conversions + GEMMs (x converted in-GEMM)
    conv_w1_kernel<<<(HID_DIM * IN_DIM + 255) / 256, 256>>>(W1);
    conv_w2_kernel<<<(OUT_DIM * HID_DIM + 255) / 256, 256>>>(W2);

    dim3 g1((M + 127) / 128, HID_DIM / 256);
    gemm1_mma_kernel<<<g1, 512, G1_SMEM>>>(x, b1, M);
    gemm2_mma_kernel<<<(M + 127) / 128, 256, G2_SMEM>>>(b2, M);

    // ---- join: hops need both the CSR and H0 ----
    cudaStreamWaitEvent(0, ev_join, 0);

    // hops 1..9, then hop 10 fused with the gated combine
    int spmm_blocks = (M * 32 + 255) / 256;
    for (int hop = 1; hop < HOPS; ++hop)
        spmm_kernel<<<spmm_blocks, 256>>>(hop, M);
    spmm_combine_kernel<<<spmm_blocks, 256>>>(s, (float*)d_out, M);
}

// round 14
// speedup vs baseline: 1.0391x; 1.0391x over previous
#include <cuda_runtime.h>
#include <cuda_fp16.h>
#include <math.h>
#include <stdint.h>

#define N_NODES 100000
#define E_MAX   3300000
#define IN_DIM  512
#define HID_DIM 512
#define OUT_DIM 64
#define HOPS    10

// ---------------- scratch (static device globals; no allocations) ----------------
__device__ __half g_h1h[(size_t)N_NODES * HID_DIM];               // 102.4 MB
__device__ __half g_Hh[(size_t)(HOPS + 1) * N_NODES * OUT_DIM];   // 140.8 MB
__device__ __half g_w1t[(size_t)HID_DIM * IN_DIM];                // 0.5 MB ([n][k])
__device__ __half g_w2t[(size_t)OUT_DIM * HID_DIM];               // 64 KB ([n][k])
__device__ int   g_deg[N_NODES];
__device__ int   g_rowptr[N_NODES + 1];
__device__ int   g_cursor[N_NODES];
__device__ int2  g_edge[E_MAX];                                   // (col, half2(w,w) bits)

// ================= PTX helpers =================
__device__ __forceinline__ uint32_t smem_u32(const void* p) {
    uint32_t a;
    asm("{ .reg .u64 t; cvta.to.shared.u64 t, %1; cvt.u32.u64 %0, t; }" : "=r"(a) : "l"(p));
    return a;
}
__device__ __forceinline__ void cp_async16(uint32_t s, const void* g, int sz) {
    asm volatile("cp.async.cg.shared.global [%0], [%1], 16, %2;"
                 :: "r"(s), "l"(g), "r"(sz) : "memory");
}
__device__ __forceinline__ void cp_commit() {
    asm volatile("cp.async.commit_group;" ::: "memory");
}
template <int N>
__device__ __forceinline__ void cp_wait() {
    asm volatile("cp.async.wait_group %0;" :: "n"(N) : "memory");
}
__device__ __forceinline__ void ldsm_x4(uint32_t* r, uint32_t addr) {
    asm volatile("ldmatrix.sync.aligned.m8n8.x4.shared.b16 {%0,%1,%2,%3}, [%4];"
                 : "=r"(r[0]), "=r"(r[1]), "=r"(r[2]), "=r"(r[3]) : "r"(addr));
}
__device__ __forceinline__ void mma_f16(float* d, const uint32_t* a, const uint32_t* b) {
    asm volatile(
        "mma.sync.aligned.m16n8k16.row.col.f32.f16.f16.f32 "
        "{%0,%1,%2,%3}, {%4,%5,%6,%7}, {%8,%9}, {%0,%1,%2,%3};"
        : "+f"(d[0]), "+f"(d[1]), "+f"(d[2]), "+f"(d[3])
        : "r"(a[0]), "r"(a[1]), "r"(a[2]), "r"(a[3]), "r"(b[0]), "r"(b[1]));
}
__device__ __forceinline__ __half2 bits2h2(int b) {
    union { int i; __half2 h; } u; u.i = b; return u.h;
}
__device__ __forceinline__ int h22bits(__half2 h) {
    union { int i; __half2 h; } u; u.h = h; return u.i;
}

// ---------------- fp16 weight conversion kernels ----------------
__global__ void conv_w1_kernel(const float* __restrict__ W1)
{
    int i = blockIdx.x * blockDim.x + threadIdx.x;  // i = n*512 + k
    if (i >= HID_DIM * IN_DIM) return;
    int n = i >> 9, k = i & 511;
    g_w1t[i] = __float2half_rn(W1[k * HID_DIM + n]);
}

__global__ void conv_w2_kernel(const float* __restrict__ W2)
{
    int i = blockIdx.x * blockDim.x + threadIdx.x;  // i = n*512 + k
    if (i >= OUT_DIM * HID_DIM) return;
    int n = i >> 9, k = i & 511;
    g_w2t[i] = __float2half_rn(W2[k * OUT_DIM + n]);
}

// ============ GEMM1 (mma.sync fp16): h1 = relu(x @ W1 + b1) -> fp16 ============
#define G1_NKC   (IN_DIM / 64)        // 8
#define G1_PA    288                  // A pitch bytes (72 words)
#define G1_PB    144                  // B pitch bytes (fp16)
#define G1_AT    (128 * G1_PA)        // 36864
#define G1_BT    (256 * G1_PB)        // 36864
#define G1_ST    (G1_AT + G1_BT)      // 73728
#define G1_SMEM  (3 * G1_ST)          // 221184

__global__ __launch_bounds__(512, 1) void gemm1_mma_kernel(
    const float* __restrict__ x, const float* __restrict__ bias, int M)
{
    extern __shared__ char smem[];
    const int tid  = threadIdx.x;
    const int wid  = tid >> 5, lane = tid & 31;
    const int wm   = wid & 3,  wn   = wid >> 2;      // 4 x 4 warps
    const int brow = blockIdx.x * 128, bcol = blockIdx.y * 256;

    const uint32_t sbase = smem_u32(smem);
    const uint32_t BOFF = G1_AT;

    float d[2][8][4];
#pragma unroll
    for (int i = 0; i < 2; i++)
#pragma unroll
        for (int j = 0; j < 8; j++)
#pragma unroll
            for (int k = 0; k < 4; k++) d[i][j][k] = 0.f;

    auto issue_load = [&](int kc, int st) {
        const int k0 = kc * 64;
        const uint32_t s0 = sbase + st * G1_ST;
#pragma unroll
        for (int i = 0; i < 4; i++) {  // A: 2048 segs of 16B (4 fp32 each)
            int seg = tid + i * 512;
            int row = seg >> 4, sc = seg & 15;
            uint32_t soff = row * G1_PA + sc * 16;
            int ar = brow + row;
            int ok = (ar < M);
            size_t gA = (size_t)(ok ? ar : 0) * IN_DIM + k0 + sc * 4;
            cp_async16(s0 + soff, x + gA, ok ? 16 : 0);
        }
#pragma unroll
        for (int i = 0; i < 4; i++) {  // B: 2048 segs (8 fp16 each)
            int seg = tid + i * 512;
            int row = seg >> 3, sc = seg & 7;
            uint32_t soff = row * G1_PB + sc * 16;
            size_t gB = (size_t)(bcol + row) * IN_DIM + k0 + sc * 8;
            cp_async16(s0 + BOFF + soff, g_w1t + gB, 16);
        }
        cp_commit();
    };

    issue_load(0, 0);
    issue_load(1, 1);

    const int g2 = lane >> 2, tq = lane & 3;

    for (int kc = 0; kc < G1_NKC; kc++) {
        if (kc == G1_NKC - 1) cp_wait<0>(); else cp_wait<1>();
        __syncthreads();
        if (kc + 2 < G1_NKC) issue_load(kc + 2, (kc + 2) % 3);

        const char*  sc8 = smem + (kc % 3) * G1_ST;
        const float* As  = (const float*)sc8;
        const uint32_t s0 = sbase + (kc % 3) * G1_ST;
#pragma unroll
        for (int ks = 0; ks < 4; ks++) {
            uint32_t a[2][4];
            const int kk = ks * 16 + tq * 2;
#pragma unroll
            for (int mt = 0; mt < 2; mt++) {
                int r0 = (wm * 32 + mt * 16 + g2) * 72;
                float2 p00 = *(const float2*)(As + r0 + kk);
                float2 p10 = *(const float2*)(As + r0 + 8 * 72 + kk);
                float2 p01 = *(const float2*)(As + r0 + kk + 8);
                float2 p11 = *(const float2*)(As + r0 + 8 * 72 + kk + 8);
                a[mt][0] = h22bits(__floats2half2_rn(p00.x, p00.y));
                a[mt][1] = h22bits(__floats2half2_rn(p10.x, p10.y));
                a[mt][2] = h22bits(__floats2half2_rn(p01.x, p01.y));
                a[mt][3] = h22bits(__floats2half2_rn(p11.x, p11.y));
            }
            const int bn_l = (lane >> 4) * 8 + (lane & 7);
            const int bk   = (ks * 16 + ((lane >> 3) & 1) * 8) * 2;
#pragma unroll
            for (int p = 0; p < 4; p++) {
                uint32_t b[4];
                int n = wn * 64 + p * 16 + bn_l;
                ldsm_x4(b, s0 + BOFF + n * G1_PB + bk);
#pragma unroll
                for (int mt = 0; mt < 2; mt++) {
#pragma unroll
                    for (int j = 0; j < 2; j++)
                        mma_f16(d[mt][2 * p + j], a[mt], b + 2 * j);
                }
            }
        }
    }

    // ---- epilogue: relu(acc + bias) -> fp16 h1
#pragma unroll
    for (int mt = 0; mt < 2; mt++) {
        int row0 = brow + wm * 32 + mt * 16 + (lane >> 2);
#pragma unroll
        for (int nt = 0; nt < 8; nt++) {
            int col = bcol + wn * 64 + nt * 8 + (lane & 3) * 2;
            float b0 = bias[col], b1 = bias[col + 1];
#pragma unroll
            for (int h = 0; h < 2; h++) {
                int r = row0 + h * 8;
                if (r >= M) continue;
                __half2 hv = __floats2half2_rn(fmaxf(d[mt][nt][2 * h + 0] + b0, 0.f),
                                               fmaxf(d[mt][nt][2 * h + 1] + b1, 0.f));
                *(__half2*)(g_h1h + (size_t)r * HID_DIM + col) = hv;
            }
        }
    }
}

// ============ GEMM2 (mma.sync fp16): H0 = h1 @ W2 + b2 -> fp16 ============
#define G2_NKC   (HID_DIM / 64)       // 8
#define G2_P     144
#define G2_AT    (128 * G2_P)         // 18432
#define G2_BT    (64 * G2_P)          // 9216
#define G2_ST    (G2_AT + G2_BT)      // 27648
#define G2_SMEM  (3 * G2_ST)          // 82944

__global__ __launch_bounds__(256, 2) void gemm2_mma_kernel(const float* __restrict__ bias, int M)
{
    extern __shared__ char smem[];
    const int tid  = threadIdx.x;
    const int wid  = tid >> 5, lane = tid & 31;
    const int wm   = wid & 3,  wn   = wid >> 2;      // 4 x 2 warps
    const int brow = blockIdx.x * 128;

    const uint32_t sbase = smem_u32(smem);
    const uint32_t AOFF = 0, BOFF = G2_AT;

    float d[2][4][4];
#pragma unroll
    for (int i = 0; i < 2; i++)
#pragma unroll
        for (int j = 0; j < 4; j++)
#pragma unroll
            for (int k = 0; k < 4; k++) d[i][j][k] = 0.f;

    auto issue_load = [&](int kc, int st) {
        const int k0 = kc * 64;
        const uint32_t s0 = sbase + st * G2_ST;
#pragma unroll
        for (int i = 0; i < 4; i++) {  // A: 1024 segs
            int seg = tid + i * 256;
            int row = seg >> 3, sc = seg & 7;
            uint32_t soff = row * G2_P + sc * 16;
            int ar = brow + row;
            int ok = (ar < M);
            size_t gA = (size_t)(ok ? ar : 0) * HID_DIM + k0 + sc * 8;
            cp_async16(s0 + AOFF + soff, g_h1h + gA, ok ? 16 : 0);
        }
#pragma unroll
        for (int i = 0; i < 2; i++) {  // B: 512 segs
            int seg = tid + i * 256;
            int row = seg >> 3, sc = seg & 7;
            uint32_t soff = row * G2_P + sc * 16;
            size_t gB = (size_t)row * HID_DIM + k0 + sc * 8;
            cp_async16(s0 + BOFF + soff, g_w2t + gB, 16);
        }
        cp_commit();
    };

    issue_load(0, 0);
    issue_load(1, 1);

    for (int kc = 0; kc < G2_NKC; kc++) {
        if (kc == G2_NKC - 1) cp_wait<0>(); else cp_wait<1>();
        __syncthreads();
        if (kc + 2 < G2_NKC) issue_load(kc + 2, (kc + 2) % 3);

        const uint32_t s0 = sbase + (kc % 3) * G2_ST;
#pragma unroll
        for (int ks = 0; ks < 4; ks++) {
            uint32_t a[2][4];
            const int ac = (ks * 16 + (lane >> 4) * 8) * 2;
#pragma unroll
            for (int mt = 0; mt < 2; mt++) {
                int r = wm * 32 + mt * 16 + (lane & 15);
                ldsm_x4(a[mt], s0 + AOFF + r * G2_P + ac);
            }
            const int bn_l = (lane >> 4) * 8 + (lane & 7);
            const int bk   = (ks * 16 + ((lane >> 3) & 1) * 8) * 2;
#pragma unroll
            for (int p = 0; p < 2; p++) {
                uint32_t b[4];
                int n = wn * 32 + p * 16 + bn_l;
                ldsm_x4(b, s0 + BOFF + n * G2_P + bk);
#pragma unroll
                for (int mt = 0; mt < 2; mt++) {
#pragma unroll
                    for (int j = 0; j < 2; j++)
                        mma_f16(d[mt][2 * p + j], a[mt], b + 2 * j);
                }
            }
        }
    }

#pragma unroll
    for (int mt = 0; mt < 2; mt++) {
        int row0 = brow + wm * 32 + mt * 16 + (lane >> 2);
#pragma unroll
        for (int nt = 0; nt < 4; nt++) {
            int col = wn * 32 + nt * 8 + (lane & 3) * 2;
            float b0 = bias[col], b1 = bias[col + 1];
#pragma unroll
            for (int h = 0; h < 2; h++) {
                int r = row0 + h * 8;
                if (r >= M) continue;
                __half2 hv = __floats2half2_rn(d[mt][nt][2 * h + 0] + b0,
                                               d[mt][nt][2 * h + 1] + b1);
                *(__half2*)(g_Hh + (size_t)r * OUT_DIM + col) = hv;
            }
        }
    }
}

// ---------------- CSR build ----------------
__global__ void zero_deg_kernel(int n)
{
    int i = blockIdx.x * blockDim.x + threadIdx.x;
    if (i < n) g_deg[i] = 0;
}

__global__ void hist_kernel(const int* __restrict__ row, int E)
{
    int e = blockIdx.x * blockDim.x + threadIdx.x;
    if (e < E) atomicAdd(&g_deg[row[e]], 1);
}

__global__ __launch_bounds__(1024) void scan_kernel(int n)
{
    __shared__ int sums[1024];
    int tid = threadIdx.x;
    int per = (n + 1023) >> 10;
    int start = tid * per;
    int end = min(start + per, n);

    int s = 0;
    for (int i = start; i < end; ++i) s += g_deg[i];
    sums[tid] = s;
    __syncthreads();

    for (int off = 1; off < 1024; off <<= 1) {
        int v = 0;
        if (tid >= off) v = sums[tid - off];
        __syncthreads();
        sums[tid] += v;
        __syncthreads();
    }

    int run = sums[tid] - s;
    for (int i = start; i < end; ++i) {
        g_rowptr[i] = run;
        g_cursor[i] = run;
        run += g_deg[i];
    }
    if (tid == 1023) g_rowptr[n] = sums[1023];
}

__global__ void scatter_kernel(const int* __restrict__ row, const int* __restrict__ col,
                               const float* __restrict__ w, int E)
{
    int e = blockIdx.x * blockDim.x + threadIdx.x;
    if (e >= E) return;
    int r = row[e];
    int pos = atomicAdd(&g_cursor[r], 1);
    __half hw = __float2half_rn(w[e]);
    __half2 w2 = __half2half2(hw);
    g_edge[pos] = make_int2(col[e], h22bits(w2));
}

// ---- shared SpMM row body (round-11 proven: UNpredicated clamped tail) ----
__device__ __forceinline__ void spmm_row(
    const __half* __restrict__ hin, int2 (*ebuf)[32], int wslot,
    int lane, int grp, int sub, int s, int e, float* f)
{
#pragma unroll
    for (int k = 0; k < 8; k++) f[k] = 0.f;

    for (int base = s; base < e; base += 32) {
        const int cnt = min(32, e - base);
        if (lane < cnt) ebuf[wslot][lane] = g_edge[base + lane];
        __syncwarp();

        __half2 hacc[4];
#pragma unroll
        for (int k = 0; k < 4; k++) hacc[k] = __float2half2_rn(0.f);

        if (cnt == 32) {
            // full batch: unrolled -> 8 independent LDG.128 in flight (MLP 8)
#pragma unroll
            for (int it = 0; it < 8; ++it) {
                int2 ed = ebuf[wslot][it * 4 + grp];
                uint4 v = *(const uint4*)(hin + (size_t)ed.x * 64 + sub * 8);
                __half2 w2 = bits2h2(ed.y);
                hacc[0] = __hfma2(w2, bits2h2((int)v.x), hacc[0]);
                hacc[1] = __hfma2(w2, bits2h2((int)v.y), hacc[1]);
                hacc[2] = __hfma2(w2, bits2h2((int)v.z), hacc[2]);
                hacc[3] = __hfma2(w2, bits2h2((int)v.w), hacc[3]);
            }
        } else {
            // tail: clamped index, zero weight (loads stay unconditional & batched)
            const int nit = (cnt + 3) >> 2;
            for (int it = 0; it < nit; ++it) {
                int ei = it * 4 + grp;
                int2 ed = ebuf[wslot][ei < cnt ? ei : 0];
                int wb  = (ei < cnt) ? ed.y : 0;
                uint4 v = *(const uint4*)(hin + (size_t)ed.x * 64 + sub * 8);
                __half2 w2 = bits2h2(wb);
                hacc[0] = __hfma2(w2, bits2h2((int)v.x), hacc[0]);
                hacc[1] = __hfma2(w2, bits2h2((int)v.y), hacc[1]);
                hacc[2] = __hfma2(w2, bits2h2((int)v.z), hacc[2]);
                hacc[3] = __hfma2(w2, bits2h2((int)v.w), hacc[3]);
            }
        }
#pragma unroll
        for (int k = 0; k < 4; k++) {
            float2 t = __half22float2(hacc[k]);
            f[2 * k]     += t.x;
            f[2 * k + 1] += t.y;
        }
        __syncwarp();
    }

    // reduce across the 4 edge groups -> all lanes hold sub-segment totals
#pragma unroll
    for (int k = 0; k < 8; k++) {
        f[k] += __shfl_xor_sync(0xffffffffu, f[k], 8);
        f[k] += __shfl_xor_sync(0xffffffffu, f[k], 16);
    }
}

// ---------------- SpMM hop (hops 1..HOPS-1) ----------------
__global__ __launch_bounds__(256) void spmm_kernel(int hop, int n)
{
    __shared__ int2 ebuf[8][32];
    const int wslot = threadIdx.x >> 5;
    const int warp  = (blockIdx.x * blockDim.x + threadIdx.x) >> 5;
    const int lane  = threadIdx.x & 31;
    if (warp >= n) return;
    const int grp = lane >> 3;
    const int sub = lane & 7;

    const __half* __restrict__ hin = g_Hh + (size_t)(hop - 1) * N_NODES * OUT_DIM;
    __half* __restrict__ hout      = g_Hh + (size_t)hop * N_NODES * OUT_DIM;

    float f[8];
    spmm_row(hin, ebuf, wslot, lane, grp, sub, g_rowptr[warp], g_rowptr[warp + 1], f);

    if (grp == 0) {
        union { __half2 h[4]; uint4 u; } o;
#pragma unroll
        for (int k = 0; k < 4; k++)
            o.h[k] = __floats2half2_rn(f[2 * k], f[2 * k + 1]);
        *(uint4*)(hout + (size_t)warp * 64 + sub * 8) = o.u;
    }
}

// ------- Final hop fused with combine (uniform-trip-count loop, converged shfls) -------
__global__ __launch_bounds__(256) void spmm_combine_kernel(
    const float* __restrict__ s, float* __restrict__ out, int n)
{
    __shared__ int2 ebuf[8][32];
    const int wslot = threadIdx.x >> 5;
    const int warp  = (blockIdx.x * blockDim.x + threadIdx.x) >> 5;
    const int lane  = threadIdx.x & 31;
    if (warp >= n) return;
    const int grp = lane >> 3;
    const int sub = lane & 7;

    const __half* __restrict__ hin = g_Hh + (size_t)(HOPS - 1) * N_NODES * OUT_DIM;

    float f[8];
    spmm_row(hin, ebuf, wslot, lane, grp, sub, g_rowptr[warp], g_rowptr[warp + 1], f);

    float sv[8];
    *(float4*)(sv)     = *(const float4*)(s + sub * 8);
    *(float4*)(sv + 4) = *(const float4*)(s + sub * 8 + 4);

    // hop-10 gate from in-register values
    float d10 = 0.f;
#pragma unroll
    for (int j = 0; j < 8; j++) d10 += f[j] * sv[j];
    d10 += __shfl_xor_sync(0xffffffffu, d10, 1);
    d10 += __shfl_xor_sync(0xffffffffu, d10, 2);
    d10 += __shfl_xor_sync(0xffffffffu, d10, 4);
    float sg10 = 1.f / (1.f + expf(-d10));

    float acc[8];
#pragma unroll
    for (int j = 0; j < 8; j++) acc[j] = (grp == 0) ? sg10 * f[j] : 0.f;

    // stored hops 0..9: uniform trip count; group g handles k = kk*4 + g (pred k<HOPS)
#pragma unroll
    for (int kk = 0; kk < 3; kk++) {
        int k = kk * 4 + grp;
        bool act = (k < HOPS);
        uint4 v = make_uint4(0, 0, 0, 0);
        if (act) {
            const __half* hk = g_Hh + (size_t)k * N_NODES * OUT_DIM
                             + (size_t)warp * 64 + sub * 8;
            v = *(const uint4*)hk;
        }
        float2 f0 = __half22float2(bits2h2((int)v.x));
        float2 f1 = __half22float2(bits2h2((int)v.y));
        float2 f2 = __half22float2(bits2h2((int)v.z));
        float2 f3 = __half22float2(bits2h2((int)v.w));
        float fv[8] = {f0.x, f0.y, f1.x, f1.y, f2.x, f2.y, f3.x, f3.y};

        float d = 0.f;
#pragma unroll
        for (int j = 0; j < 8; j++) d += fv[j] * sv[j];
        d += __shfl_xor_sync(0xffffffffu, d, 1);
        d += __shfl_xor_sync(0xffffffffu, d, 2);
        d += __shfl_xor_sync(0xffffffffu, d, 4);
        float sg = 1.f / (1.f + expf(-d));
        if (act) {
#pragma unroll
            for (int j = 0; j < 8; j++) acc[j] += sg * fv[j];
        }
    }

    // sum group contributions
#pragma unroll
    for (int j = 0; j < 8; j++) {
        acc[j] += __shfl_xor_sync(0xffffffffu, acc[j], 8);
        acc[j] += __shfl_xor_sync(0xffffffffu, acc[j], 16);
    }
    if (grp == 0) {
        float* dst = out + (size_t)warp * 64 + sub * 8;
        *(float4*)(dst)     = *(float4*)(acc);
        *(float4*)(dst + 4) = *(float4*)(acc + 4);
    }
}

// ---------------- launch ----------------
extern "C" void kernel_launch(void* const* d_in, const int* in_sizes, int n_in,
                              void* d_out, int out_size)
{
    const float* x   = (const float*)d_in[0];
    const int*   row = (const int*)  d_in[1];
    const int*   col = (const int*)  d_in[2];
    const float* ew  = (const float*)d_in[3];
    const float* W1  = (const float*)d_in[4];
    const float* b1  = (const float*)d_in[5];
    const float* W2  = (const float*)d_in[6];
    const float* b2  = (const float*)d_in[7];
    const float* s   = (const float*)d_in[8];

    int M = in_sizes[0] / IN_DIM;  // 100000
    int E = in_sizes[1];           // 3300000

    static bool attr_set = false;
    static cudaStream_t s_csr = 0;
    static cudaEvent_t ev_fork = 0, ev_join = 0;
    if (!attr_set) {
        cudaFuncSetAttribute(gemm1_mma_kernel,
                             cudaFuncAttributeMaxDynamicSharedMemorySize, G1_SMEM);
        cudaFuncSetAttribute(gemm2_mma_kernel,
                             cudaFuncAttributeMaxDynamicSharedMemorySize, G2_SMEM);
        cudaStreamCreateWithFlags(&s_csr, cudaStreamNonBlocking);
        cudaEventCreateWithFlags(&ev_fork, cudaEventDisableTiming);
        cudaEventCreateWithFlags(&ev_join, cudaEventDisableTiming);
        attr_set = true;
    }

    // ---- fork: CSR build runs concurrently with conversions + GEMMs ----
    cudaEventRecord(ev_fork, 0);
    cudaStreamWaitEvent(s_csr, ev_fork, 0);
    zero_deg_kernel<<<(M + 255) / 256, 256, 0, s_csr>>>(M);
    hist_kernel<<<(E + 255) / 256, 256, 0, s_csr>>>(row, E);
    scan_kernel<<<1, 1024, 0, s_csr>>>(M);
    scatter_kernel<<<(E + 255) / 256, 256, 0, s_csr>>>(row, col, ew, E);
    cudaEventRecord(ev_join, s_csr);

    // main stream: weight conversions + GEMMs (x converted in-GEMM)
    conv_w1_kernel<<<(HID_DIM * IN_DIM + 255) / 256, 256>>>(W1);
    conv_w2_kernel<<<(OUT_DIM * HID_DIM + 255) / 256, 256>>>(W2);

    dim3 g1((M + 127) / 128, HID_DIM / 256);
    gemm1_mma_kernel<<<g1, 512, G1_SMEM>>>(x, b1, M);
    gemm2_mma_kernel<<<(M + 127) / 128, 256, G2_SMEM>>>(b2, M);

    // ---- join: hops need both the CSR and H0 ----
    cudaStreamWaitEvent(0, ev_join, 0);

    // hops 1..9, then hop 10 fused with the gated combine
    int spmm_blocks = (M * 32 + 255) / 256;
    for (int hop = 1; hop < HOPS; ++hop)
        spmm_kernel<<<spmm_blocks, 256>>>(hop, M);
    spmm_combine_kernel<<<spmm_blocks, 256>>>(s, (float*)d_out, M);
}

// round 15
// speedup vs baseline: 1.0560x; 1.0163x over previous
#include <cuda_runtime.h>
#include <cuda_fp16.h>
#include <math.h>
#include <stdint.h>

#define N_NODES 100000
#define E_MAX   3300000
#define IN_DIM  512
#define HID_DIM 512
#define OUT_DIM 64
#define HOPS    10

// ---------------- scratch (static device globals; no allocations) ----------------
__device__ __half g_h1h[(size_t)N_NODES * HID_DIM];               // 102.4 MB
__device__ __half g_Hh[(size_t)(HOPS + 1) * N_NODES * OUT_DIM];   // 140.8 MB
__device__ __half g_w1t[(size_t)HID_DIM * IN_DIM];                // 0.5 MB ([n][k])
__device__ __half g_w2t[(size_t)OUT_DIM * HID_DIM];               // 64 KB ([n][k])
__device__ int   g_deg[N_NODES];
__device__ int   g_rowptr[N_NODES + 1];
__device__ int   g_cursor[N_NODES];
__device__ int2  g_edge[E_MAX];                                   // (col, half2(w,w) bits)

// ================= PTX helpers =================
__device__ __forceinline__ uint32_t smem_u32(const void* p) {
    uint32_t a;
    asm("{ .reg .u64 t; cvta.to.shared.u64 t, %1; cvt.u32.u64 %0, t; }" : "=r"(a) : "l"(p));
    return a;
}
__device__ __forceinline__ void cp_async16(uint32_t s, const void* g, int sz) {
    asm volatile("cp.async.cg.shared.global [%0], [%1], 16, %2;"
                 :: "r"(s), "l"(g), "r"(sz) : "memory");
}
__device__ __forceinline__ void cp_commit() {
    asm volatile("cp.async.commit_group;" ::: "memory");
}
template <int N>
__device__ __forceinline__ void cp_wait() {
    asm volatile("cp.async.wait_group %0;" :: "n"(N) : "memory");
}
__device__ __forceinline__ void ldsm_x4(uint32_t* r, uint32_t addr) {
    asm volatile("ldmatrix.sync.aligned.m8n8.x4.shared.b16 {%0,%1,%2,%3}, [%4];"
                 : "=r"(r[0]), "=r"(r[1]), "=r"(r[2]), "=r"(r[3]) : "r"(addr));
}
__device__ __forceinline__ void mma_f16(float* d, const uint32_t* a, const uint32_t* b) {
    asm volatile(
        "mma.sync.aligned.m16n8k16.row.col.f32.f16.f16.f32 "
        "{%0,%1,%2,%3}, {%4,%5,%6,%7}, {%8,%9}, {%0,%1,%2,%3};"
        : "+f"(d[0]), "+f"(d[1]), "+f"(d[2]), "+f"(d[3])
        : "r"(a[0]), "r"(a[1]), "r"(a[2]), "r"(a[3]), "r"(b[0]), "r"(b[1]));
}
__device__ __forceinline__ __half2 bits2h2(int b) {
    union { int i; __half2 h; } u; u.i = b; return u.h;
}
__device__ __forceinline__ int h22bits(__half2 h) {
    union { int i; __half2 h; } u; u.h = h; return u.i;
}

// ---------------- fp16 weight conversion kernels ----------------
__global__ void conv_w1_kernel(const float* __restrict__ W1)
{
    int i = blockIdx.x * blockDim.x + threadIdx.x;  // i = n*512 + k
    if (i >= HID_DIM * IN_DIM) return;
    int n = i >> 9, k = i & 511;
    g_w1t[i] = __float2half_rn(W1[k * HID_DIM + n]);
}

__global__ void conv_w2_kernel(const float* __restrict__ W2)
{
    int i = blockIdx.x * blockDim.x + threadIdx.x;  // i = n*512 + k
    if (i >= OUT_DIM * HID_DIM) return;
    int n = i >> 9, k = i & 511;
    g_w2t[i] = __float2half_rn(W2[k * OUT_DIM + n]);
}

// ============ GEMM1 (mma.sync fp16): h1 = relu(x @ W1 + b1) -> fp16 ============
// CTA 128x256, 16 warps (4M x 4N), warp tile 32x64. K chunks of 64, 3-stage.
// A loaded as FP32 directly from x; A fragments via LDS.64 + f32->f16x2 pack.
#define G1_NKC   (IN_DIM / 64)        // 8
#define G1_PA    288                  // A pitch bytes (72 words: conflict-free)
#define G1_PB    144                  // B pitch bytes (fp16)
#define G1_AT    (128 * G1_PA)        // 36864
#define G1_BT    (256 * G1_PB)        // 36864
#define G1_ST    (G1_AT + G1_BT)      // 73728
#define G1_SMEM  (3 * G1_ST)          // 221184

__global__ __launch_bounds__(512, 1) void gemm1_mma_kernel(
    const float* __restrict__ x, const float* __restrict__ bias, int M)
{
    extern __shared__ char smem[];
    const int tid  = threadIdx.x;
    const int wid  = tid >> 5, lane = tid & 31;
    const int wm   = wid & 3,  wn   = wid >> 2;      // 4 x 4 warps
    const int brow = blockIdx.x * 128, bcol = blockIdx.y * 256;

    const uint32_t sbase = smem_u32(smem);
    const uint32_t BOFF = G1_AT;

    float d[2][8][4];
#pragma unroll
    for (int i = 0; i < 2; i++)
#pragma unroll
        for (int j = 0; j < 8; j++)
#pragma unroll
            for (int k = 0; k < 4; k++) d[i][j][k] = 0.f;

    auto issue_load = [&](int kc, int st) {
        const int k0 = kc * 64;
        const uint32_t s0 = sbase + st * G1_ST;
#pragma unroll
        for (int i = 0; i < 4; i++) {  // A: 2048 segs of 16B (4 fp32 each)
            int seg = tid + i * 512;
            int row = seg >> 4, sc = seg & 15;
            uint32_t soff = row * G1_PA + sc * 16;
            int ar = brow + row;
            int ok = (ar < M);
            size_t gA = (size_t)(ok ? ar : 0) * IN_DIM + k0 + sc * 4;
            cp_async16(s0 + soff, x + gA, ok ? 16 : 0);
        }
#pragma unroll
        for (int i = 0; i < 4; i++) {  // B: 2048 segs (8 fp16 each)
            int seg = tid + i * 512;
            int row = seg >> 3, sc = seg & 7;
            uint32_t soff = row * G1_PB + sc * 16;
            size_t gB = (size_t)(bcol + row) * IN_DIM + k0 + sc * 8;
            cp_async16(s0 + BOFF + soff, g_w1t + gB, 16);
        }
        cp_commit();
    };

    issue_load(0, 0);
    issue_load(1, 1);

    const int g2 = lane >> 2, tq = lane & 3;

    for (int kc = 0; kc < G1_NKC; kc++) {
        if (kc == G1_NKC - 1) cp_wait<0>(); else cp_wait<1>();
        __syncthreads();
        if (kc + 2 < G1_NKC) issue_load(kc + 2, (kc + 2) % 3);

        const char*  sc8 = smem + (kc % 3) * G1_ST;
        const float* As  = (const float*)sc8;
        const uint32_t s0 = sbase + (kc % 3) * G1_ST;
#pragma unroll
        for (int ks = 0; ks < 4; ks++) {
            uint32_t a[2][4];
            const int kk = ks * 16 + tq * 2;
#pragma unroll
            for (int mt = 0; mt < 2; mt++) {
                int r0 = (wm * 32 + mt * 16 + g2) * 72;
                float2 p00 = *(const float2*)(As + r0 + kk);
                float2 p10 = *(const float2*)(As + r0 + 8 * 72 + kk);
                float2 p01 = *(const float2*)(As + r0 + kk + 8);
                float2 p11 = *(const float2*)(As + r0 + 8 * 72 + kk + 8);
                a[mt][0] = h22bits(__floats2half2_rn(p00.x, p00.y));
                a[mt][1] = h22bits(__floats2half2_rn(p10.x, p10.y));
                a[mt][2] = h22bits(__floats2half2_rn(p01.x, p01.y));
                a[mt][3] = h22bits(__floats2half2_rn(p11.x, p11.y));
            }
            const int bn_l = (lane >> 4) * 8 + (lane & 7);
            const int bk   = (ks * 16 + ((lane >> 3) & 1) * 8) * 2;
#pragma unroll
            for (int p = 0; p < 4; p++) {
                uint32_t b[4];
                int n = wn * 64 + p * 16 + bn_l;
                ldsm_x4(b, s0 + BOFF + n * G1_PB + bk);
#pragma unroll
                for (int mt = 0; mt < 2; mt++) {
#pragma unroll
                    for (int j = 0; j < 2; j++)
                        mma_f16(d[mt][2 * p + j], a[mt], b + 2 * j);
                }
            }
        }
    }

    // ---- epilogue: relu(acc + bias) -> fp16 h1
#pragma unroll
    for (int mt = 0; mt < 2; mt++) {
        int row0 = brow + wm * 32 + mt * 16 + (lane >> 2);
#pragma unroll
        for (int nt = 0; nt < 8; nt++) {
            int col = bcol + wn * 64 + nt * 8 + (lane & 3) * 2;
            float b0 = bias[col], b1 = bias[col + 1];
#pragma unroll
            for (int h = 0; h < 2; h++) {
                int r = row0 + h * 8;
                if (r >= M) continue;
                __half2 hv = __floats2half2_rn(fmaxf(d[mt][nt][2 * h + 0] + b0, 0.f),
                                               fmaxf(d[mt][nt][2 * h + 1] + b1, 0.f));
                *(__half2*)(g_h1h + (size_t)r * HID_DIM + col) = hv;
            }
        }
    }
}

// ============ GEMM2 (mma.sync fp16): H0 = h1 @ W2 + b2 -> fp16 ============
#define G2_NKC   (HID_DIM / 64)       // 8
#define G2_P     144
#define G2_AT    (128 * G2_P)         // 18432
#define G2_BT    (64 * G2_P)          // 9216
#define G2_ST    (G2_AT + G2_BT)      // 27648
#define G2_SMEM  (3 * G2_ST)          // 82944

__global__ __launch_bounds__(256, 2) void gemm2_mma_kernel(const float* __restrict__ bias, int M)
{
    extern __shared__ char smem[];
    const int tid  = threadIdx.x;
    const int wid  = tid >> 5, lane = tid & 31;
    const int wm   = wid & 3,  wn   = wid >> 2;      // 4 x 2 warps
    const int brow = blockIdx.x * 128;

    const uint32_t sbase = smem_u32(smem);
    const uint32_t AOFF = 0, BOFF = G2_AT;

    float d[2][4][4];
#pragma unroll
    for (int i = 0; i < 2; i++)
#pragma unroll
        for (int j = 0; j < 4; j++)
#pragma unroll
            for (int k = 0; k < 4; k++) d[i][j][k] = 0.f;

    auto issue_load = [&](int kc, int st) {
        const int k0 = kc * 64;
        const uint32_t s0 = sbase + st * G2_ST;
#pragma unroll
        for (int i = 0; i < 4; i++) {  // A: 1024 segs
            int seg = tid + i * 256;
            int row = seg >> 3, sc = seg & 7;
            uint32_t soff = row * G2_P + sc * 16;
            int ar = brow + row;
            int ok = (ar < M);
            size_t gA = (size_t)(ok ? ar : 0) * HID_DIM + k0 + sc * 8;
            cp_async16(s0 + AOFF + soff, g_h1h + gA, ok ? 16 : 0);
        }
#pragma unroll
        for (int i = 0; i < 2; i++) {  // B: 512 segs
            int seg = tid + i * 256;
            int row = seg >> 3, sc = seg & 7;
            uint32_t soff = row * G2_P + sc * 16;
            size_t gB = (size_t)row * HID_DIM + k0 + sc * 8;
            cp_async16(s0 + BOFF + soff, g_w2t + gB, 16);
        }
        cp_commit();
    };

    issue_load(0, 0);
    issue_load(1, 1);

    for (int kc = 0; kc < G2_NKC; kc++) {
        if (kc == G2_NKC - 1) cp_wait<0>(); else cp_wait<1>();
        __syncthreads();
        if (kc + 2 < G2_NKC) issue_load(kc + 2, (kc + 2) % 3);

        const uint32_t s0 = sbase + (kc % 3) * G2_ST;
#pragma unroll
        for (int ks = 0; ks < 4; ks++) {
            uint32_t a[2][4];
            const int ac = (ks * 16 + (lane >> 4) * 8) * 2;
#pragma unroll
            for (int mt = 0; mt < 2; mt++) {
                int r = wm * 32 + mt * 16 + (lane & 15);
                ldsm_x4(a[mt], s0 + AOFF + r * G2_P + ac);
            }
            const int bn_l = (lane >> 4) * 8 + (lane & 7);
            const int bk   = (ks * 16 + ((lane >> 3) & 1) * 8) * 2;
#pragma unroll
            for (int p = 0; p < 2; p++) {
                uint32_t b[4];
                int n = wn * 32 + p * 16 + bn_l;
                ldsm_x4(b, s0 + BOFF + n * G2_P + bk);
#pragma unroll
                for (int mt = 0; mt < 2; mt++) {
#pragma unroll
                    for (int j = 0; j < 2; j++)
                        mma_f16(d[mt][2 * p + j], a[mt], b + 2 * j);
                }
            }
        }
    }

    // ---- epilogue: + bias, write fp16 H0
#pragma unroll
    for (int mt = 0; mt < 2; mt++) {
        int row0 = brow + wm * 32 + mt * 16 + (lane >> 2);
#pragma unroll
        for (int nt = 0; nt < 4; nt++) {
            int col = wn * 32 + nt * 8 + (lane & 3) * 2;
            float b0 = bias[col], b1 = bias[col + 1];
#pragma unroll
            for (int h = 0; h < 2; h++) {
                int r = row0 + h * 8;
                if (r >= M) continue;
                __half2 hv = __floats2half2_rn(d[mt][nt][2 * h + 0] + b0,
                                               d[mt][nt][2 * h + 1] + b1);
                *(__half2*)(g_Hh + (size_t)r * OUT_DIM + col) = hv;
            }
        }
    }
}

// ---------------- CSR build ----------------
__global__ void zero_deg_kernel(int n)
{
    int i = blockIdx.x * blockDim.x + threadIdx.x;
    if (i < n) g_deg[i] = 0;
}

__global__ void hist_kernel(const int* __restrict__ row, int E)
{
    int e = blockIdx.x * blockDim.x + threadIdx.x;
    if (e < E) atomicAdd(&g_deg[row[e]], 1);
}

__global__ __launch_bounds__(1024) void scan_kernel(int n)
{
    __shared__ int sums[1024];
    int tid = threadIdx.x;
    int per = (n + 1023) >> 10;
    int start = tid * per;
    int end = min(start + per, n);

    int s = 0;
    for (int i = start; i < end; ++i) s += g_deg[i];
    sums[tid] = s;
    __syncthreads();

    for (int off = 1; off < 1024; off <<= 1) {
        int v = 0;
        if (tid >= off) v = sums[tid - off];
        __syncthreads();
        sums[tid] += v;
        __syncthreads();
    }

    int run = sums[tid] - s;
    for (int i = start; i < end; ++i) {
        g_rowptr[i] = run;
        g_cursor[i] = run;
        run += g_deg[i];
    }
    if (tid == 1023) g_rowptr[n] = sums[1023];
}

__global__ void scatter_kernel(const int* __restrict__ row, const int* __restrict__ col,
                               const float* __restrict__ w, int E)
{
    int e = blockIdx.x * blockDim.x + threadIdx.x;
    if (e >= E) return;
    int r = row[e];
    int pos = atomicAdd(&g_cursor[r], 1);
    __half hw = __float2half_rn(w[e]);
    __half2 w2 = __half2half2(hw);
    g_edge[pos] = make_int2(col[e], h22bits(w2));
}

// ---------------- SpMM hop: 4 edges per LDG.128, MLP-8 fast path ----------------
__global__ __launch_bounds__(256) void spmm_kernel(int hop, int n)
{
    __shared__ int2 ebuf[8][32];
    const int wslot = threadIdx.x >> 5;
    const int warp  = (blockIdx.x * blockDim.x + threadIdx.x) >> 5;
    const int lane  = threadIdx.x & 31;
    if (warp >= n) return;
    const int grp = lane >> 3;
    const int sub = lane & 7;

    const __half* __restrict__ hin = g_Hh + (size_t)(hop - 1) * N_NODES * OUT_DIM;
    __half* __restrict__ hout      = g_Hh + (size_t)hop * N_NODES * OUT_DIM;

    const int s = g_rowptr[warp];
    const int e = g_rowptr[warp + 1];

    float f[8];
#pragma unroll
    for (int k = 0; k < 8; k++) f[k] = 0.f;

    for (int base = s; base < e; base += 32) {
        const int cnt = min(32, e - base);
        if (lane < cnt) ebuf[wslot][lane] = g_edge[base + lane];
        __syncwarp();

        __half2 hacc[4];
#pragma unroll
        for (int k = 0; k < 4; k++) hacc[k] = __float2half2_rn(0.f);

        if (cnt == 32) {
            // full batch: unrolled -> 8 independent LDG.128 in flight (MLP 8)
#pragma unroll
            for (int it = 0; it < 8; ++it) {
                int2 ed = ebuf[wslot][it * 4 + grp];
                uint4 v = *(const uint4*)(hin + (size_t)ed.x * 64 + sub * 8);
                __half2 w2 = bits2h2(ed.y);
                hacc[0] = __hfma2(w2, bits2h2((int)v.x), hacc[0]);
                hacc[1] = __hfma2(w2, bits2h2((int)v.y), hacc[1]);
                hacc[2] = __hfma2(w2, bits2h2((int)v.z), hacc[2]);
                hacc[3] = __hfma2(w2, bits2h2((int)v.w), hacc[3]);
            }
        } else {
            const int nit = (cnt + 3) >> 2;
            for (int it = 0; it < nit; ++it) {
                int ei = it * 4 + grp;
                int2 ed = ebuf[wslot][ei < cnt ? ei : 0];
                int wb  = (ei < cnt) ? ed.y : 0;
                uint4 v = *(const uint4*)(hin + (size_t)ed.x * 64 + sub * 8);
                __half2 w2 = bits2h2(wb);
                hacc[0] = __hfma2(w2, bits2h2((int)v.x), hacc[0]);
                hacc[1] = __hfma2(w2, bits2h2((int)v.y), hacc[1]);
                hacc[2] = __hfma2(w2, bits2h2((int)v.z), hacc[2]);
                hacc[3] = __hfma2(w2, bits2h2((int)v.w), hacc[3]);
            }
        }
#pragma unroll
        for (int k = 0; k < 4; k++) {
            float2 t = __half22float2(hacc[k]);
            f[2 * k]     += t.x;
            f[2 * k + 1] += t.y;
        }
        __syncwarp();
    }

    // reduce across the 4 edge groups
#pragma unroll
    for (int k = 0; k < 8; k++) {
        f[k] += __shfl_xor_sync(0xffffffffu, f[k], 8);
        f[k] += __shfl_xor_sync(0xffffffffu, f[k], 16);
    }
    if (grp == 0) {
        union { __half2 h[4]; uint4 u; } o;
#pragma unroll
        for (int k = 0; k < 4; k++)
            o.h[k] = __floats2half2_rn(f[2 * k], f[2 * k + 1]);
        *(uint4*)(hout + (size_t)warp * 64 + sub * 8) = o.u;
    }
}

// ---------------- Combine: 4 rows/warp, vectorized uint4 loads ----------------
__global__ __launch_bounds__(256) void combine_kernel(
    const float* __restrict__ s, float* __restrict__ out, int n)
{
    const int warp = (blockIdx.x * blockDim.x + threadIdx.x) >> 5;
    const int lane = threadIdx.x & 31;
    const int g   = lane >> 3;
    const int sub = lane & 7;
    int row = warp * 4 + g;
    const bool valid = (row < n);
    if (warp * 4 >= n) return;          // whole warp out of range
    if (!valid) row = n - 1;            // clamp loads, guard store

    float sv[8];
    *(float4*)(sv)     = *(const float4*)(s + sub * 8);
    *(float4*)(sv + 4) = *(const float4*)(s + sub * 8 + 4);

    float acc[8];
#pragma unroll
    for (int j = 0; j < 8; j++) acc[j] = 0.f;

#pragma unroll
    for (int k = 0; k <= HOPS; k++) {
        const __half* hk = g_Hh + (size_t)k * N_NODES * OUT_DIM + (size_t)row * 64 + sub * 8;
        uint4 v = *(const uint4*)hk;
        float2 f0 = __half22float2(bits2h2((int)v.x));
        float2 f1 = __half22float2(bits2h2((int)v.y));
        float2 f2 = __half22float2(bits2h2((int)v.z));
        float2 f3 = __half22float2(bits2h2((int)v.w));
        float fv[8] = {f0.x, f0.y, f1.x, f1.y, f2.x, f2.y, f3.x, f3.y};

        float d = 0.f;
#pragma unroll
        for (int j = 0; j < 8; j++) d += fv[j] * sv[j];
        d += __shfl_xor_sync(0xffffffffu, d, 1);
        d += __shfl_xor_sync(0xffffffffu, d, 2);
        d += __shfl_xor_sync(0xffffffffu, d, 4);
        float sg = 1.f / (1.f + expf(-d));
#pragma unroll
        for (int j = 0; j < 8; j++) acc[j] += sg * fv[j];
    }
    if (valid) {
        float* dst = out + (size_t)row * 64 + sub * 8;
        *(float4*)(dst)     = *(float4*)(acc);
        *(float4*)(dst + 4) = *(float4*)(acc + 4);
    }
}

// ---------------- launch (round-11 proven configuration) ----------------
extern "C" void kernel_launch(void* const* d_in, const int* in_sizes, int n_in,
                              void* d_out, int out_size)
{
    const float* x   = (const float*)d_in[0];
    const int*   row = (const int*)  d_in[1];
    const int*   col = (const int*)  d_in[2];
    const float* ew  = (const float*)d_in[3];
    const float* W1  = (const float*)d_in[4];
    const float* b1  = (const float*)d_in[5];
    const float* W2  = (const float*)d_in[6];
    const float* b2  = (const float*)d_in[7];
    const float* s   = (const float*)d_in[8];

    int M = in_sizes[0] / IN_DIM;  // 100000
    int E = in_sizes[1];           // 3300000

    static bool attr_set = false;
    static cudaStream_t s_csr = 0;
    static cudaEvent_t ev_fork = 0, ev_join = 0;
    if (!attr_set) {
        cudaFuncSetAttribute(gemm1_mma_kernel,
                             cudaFuncAttributeMaxDynamicSharedMemorySize, G1_SMEM);
        cudaFuncSetAttribute(gemm2_mma_kernel,
                             cudaFuncAttributeMaxDynamicSharedMemorySize, G2_SMEM);
        cudaStreamCreateWithFlags(&s_csr, cudaStreamNonBlocking);
        cudaEventCreateWithFlags(&ev_fork, cudaEventDisableTiming);
        cudaEventCreateWithFlags(&ev_join, cudaEventDisableTiming);
        attr_set = true;
    }

    // ---- fork: CSR build runs concurrently with conversions + GEMMs ----
    cudaEventRecord(ev_fork, 0);
    cudaStreamWaitEvent(s_csr, ev_fork, 0);
    zero_deg_kernel<<<(M + 255) / 256, 256, 0, s_csr>>>(M);
    hist_kernel<<<(E + 255) / 256, 256, 0, s_csr>>>(row, E);
    scan_kernel<<<1, 1024, 0, s_csr>>>(M);
    scatter_kernel<<<(E + 255) / 256, 256, 0, s_csr>>>(row, col, ew, E);
    cudaEventRecord(ev_join, s_csr);

    // main stream: weight conversions + GEMMs (x converted in-GEMM)
    conv_w1_kernel<<<(HID_DIM * IN_DIM + 255) / 256, 256>>>(W1);
    conv_w2_kernel<<<(OUT_DIM * HID_DIM + 255) / 256, 256>>>(W2);

    dim3 g1((M + 127) / 128, HID_DIM / 256);
    gemm1_mma_kernel<<<g1, 512, G1_SMEM>>>(x, b1, M);
    gemm2_mma_kernel<<<(M + 127) / 128, 256, G2_SMEM>>>(b2, M);

    // ---- join: hops need both the CSR and H0 ----
    cudaStreamWaitEvent(0, ev_join, 0);

    // 10 propagation hops (fp16 features)
    int spmm_blocks = (M * 32 + 255) / 256;
    for (int hop = 1; hop <= HOPS; ++hop)
        spmm_kernel<<<spmm_blocks, 256>>>(hop, M);

    // gated combine (4 rows per warp)
    int comb_warps = (M + 3) / 4;
    combine_kernel<<<(comb_warps * 32 + 255) / 256, 256>>>(s, (float*)d_out, M);
}

// round 16
// speedup vs baseline: 1.0738x; 1.0168x over previous
#include <cuda_runtime.h>
#include <cuda_fp16.h>
#include <math.h>
#include <stdint.h>

#define N_NODES 100000
#define E_MAX   3300000
#define IN_DIM  512
#define HID_DIM 512
#define OUT_DIM 64
#define HOPS    10

// ---------------- scratch (static device globals; no allocations) ----------------
__device__ __half g_h1h[(size_t)N_NODES * HID_DIM];               // 102.4 MB
__device__ __half g_Hh[(size_t)(HOPS + 1) * N_NODES * OUT_DIM];   // 140.8 MB
__device__ __half g_w1t[(size_t)HID_DIM * IN_DIM];                // 0.5 MB ([n][k])
__device__ __half g_w2t[(size_t)OUT_DIM * HID_DIM];               // 64 KB ([n][k])
__device__ int   g_deg[N_NODES];
__device__ int   g_rowptr[N_NODES + 1];
__device__ int   g_cursor[N_NODES];
__device__ int2  g_edge[E_MAX];                                   // (col, half2(w,w) bits)
__device__ int   g_bar;                                           // persistent-kernel barrier

// ================= PTX helpers =================
__device__ __forceinline__ uint32_t smem_u32(const void* p) {
    uint32_t a;
    asm("{ .reg .u64 t; cvta.to.shared.u64 t, %1; cvt.u32.u64 %0, t; }" : "=r"(a) : "l"(p));
    return a;
}
__device__ __forceinline__ void cp_async16(uint32_t s, const void* g, int sz) {
    asm volatile("cp.async.cg.shared.global [%0], [%1], 16, %2;"
                 :: "r"(s), "l"(g), "r"(sz) : "memory");
}
__device__ __forceinline__ void cp_commit() {
    asm volatile("cp.async.commit_group;" ::: "memory");
}
template <int N>
__device__ __forceinline__ void cp_wait() {
    asm volatile("cp.async.wait_group %0;" :: "n"(N) : "memory");
}
__device__ __forceinline__ void ldsm_x4(uint32_t* r, uint32_t addr) {
    asm volatile("ldmatrix.sync.aligned.m8n8.x4.shared.b16 {%0,%1,%2,%3}, [%4];"
                 : "=r"(r[0]), "=r"(r[1]), "=r"(r[2]), "=r"(r[3]) : "r"(addr));
}
__device__ __forceinline__ void mma_f16(float* d, const uint32_t* a, const uint32_t* b) {
    asm volatile(
        "mma.sync.aligned.m16n8k16.row.col.f32.f16.f16.f32 "
        "{%0,%1,%2,%3}, {%4,%5,%6,%7}, {%8,%9}, {%0,%1,%2,%3};"
        : "+f"(d[0]), "+f"(d[1]), "+f"(d[2]), "+f"(d[3])
        : "r"(a[0]), "r"(a[1]), "r"(a[2]), "r"(a[3]), "r"(b[0]), "r"(b[1]));
}
__device__ __forceinline__ __half2 bits2h2(int b) {
    union { int i; __half2 h; } u; u.i = b; return u.h;
}
__device__ __forceinline__ int h22bits(__half2 h) {
    union { int i; __half2 h; } u; u.h = h; return u.i;
}

// ---------------- fp16 weight conversion kernels ----------------
__global__ void conv_w1_kernel(const float* __restrict__ W1)
{
    int i = blockIdx.x * blockDim.x + threadIdx.x;  // i = n*512 + k
    if (i >= HID_DIM * IN_DIM) return;
    int n = i >> 9, k = i & 511;
    g_w1t[i] = __float2half_rn(W1[k * HID_DIM + n]);
}

__global__ void conv_w2_kernel(const float* __restrict__ W2)
{
    int i = blockIdx.x * blockDim.x + threadIdx.x;  // i = n*512 + k
    if (i >= OUT_DIM * HID_DIM) return;
    int n = i >> 9, k = i & 511;
    g_w2t[i] = __float2half_rn(W2[k * OUT_DIM + n]);
}

// ============ GEMM1 (mma.sync fp16): h1 = relu(x @ W1 + b1) -> fp16 ============
#define G1_NKC   (IN_DIM / 64)        // 8
#define G1_PA    288                  // A pitch bytes (72 words: conflict-free)
#define G1_PB    144                  // B pitch bytes (fp16)
#define G1_AT    (128 * G1_PA)        // 36864
#define G1_BT    (256 * G1_PB)        // 36864
#define G1_ST    (G1_AT + G1_BT)      // 73728
#define G1_SMEM  (3 * G1_ST)          // 221184

__global__ __launch_bounds__(512, 1) void gemm1_mma_kernel(
    const float* __restrict__ x, const float* __restrict__ bias, int M)
{
    extern __shared__ char smem[];
    const int tid  = threadIdx.x;
    const int wid  = tid >> 5, lane = tid & 31;
    const int wm   = wid & 3,  wn   = wid >> 2;      // 4 x 4 warps
    const int brow = blockIdx.x * 128, bcol = blockIdx.y * 256;

    const uint32_t sbase = smem_u32(smem);
    const uint32_t BOFF = G1_AT;

    float d[2][8][4];
#pragma unroll
    for (int i = 0; i < 2; i++)
#pragma unroll
        for (int j = 0; j < 8; j++)
#pragma unroll
            for (int k = 0; k < 4; k++) d[i][j][k] = 0.f;

    auto issue_load = [&](int kc, int st) {
        const int k0 = kc * 64;
        const uint32_t s0 = sbase + st * G1_ST;
#pragma unroll
        for (int i = 0; i < 4; i++) {  // A: 2048 segs of 16B (4 fp32 each)
            int seg = tid + i * 512;
            int row = seg >> 4, sc = seg & 15;
            uint32_t soff = row * G1_PA + sc * 16;
            int ar = brow + row;
            int ok = (ar < M);
            size_t gA = (size_t)(ok ? ar : 0) * IN_DIM + k0 + sc * 4;
            cp_async16(s0 + soff, x + gA, ok ? 16 : 0);
        }
#pragma unroll
        for (int i = 0; i < 4; i++) {  // B: 2048 segs (8 fp16 each)
            int seg = tid + i * 512;
            int row = seg >> 3, sc = seg & 7;
            uint32_t soff = row * G1_PB + sc * 16;
            size_t gB = (size_t)(bcol + row) * IN_DIM + k0 + sc * 8;
            cp_async16(s0 + BOFF + soff, g_w1t + gB, 16);
        }
        cp_commit();
    };

    issue_load(0, 0);
    issue_load(1, 1);

    const int g2 = lane >> 2, tq = lane & 3;

    for (int kc = 0; kc < G1_NKC; kc++) {
        if (kc == G1_NKC - 1) cp_wait<0>(); else cp_wait<1>();
        __syncthreads();
        if (kc + 2 < G1_NKC) issue_load(kc + 2, (kc + 2) % 3);

        const char*  sc8 = smem + (kc % 3) * G1_ST;
        const float* As  = (const float*)sc8;
        const uint32_t s0 = sbase + (kc % 3) * G1_ST;
#pragma unroll
        for (int ks = 0; ks < 4; ks++) {
            uint32_t a[2][4];
            const int kk = ks * 16 + tq * 2;
#pragma unroll
            for (int mt = 0; mt < 2; mt++) {
                int r0 = (wm * 32 + mt * 16 + g2) * 72;
                float2 p00 = *(const float2*)(As + r0 + kk);
                float2 p10 = *(const float2*)(As + r0 + 8 * 72 + kk);
                float2 p01 = *(const float2*)(As + r0 + kk + 8);
                float2 p11 = *(const float2*)(As + r0 + 8 * 72 + kk + 8);
                a[mt][0] = h22bits(__floats2half2_rn(p00.x, p00.y));
                a[mt][1] = h22bits(__floats2half2_rn(p10.x, p10.y));
                a[mt][2] = h22bits(__floats2half2_rn(p01.x, p01.y));
                a[mt][3] = h22bits(__floats2half2_rn(p11.x, p11.y));
            }
            const int bn_l = (lane >> 4) * 8 + (lane & 7);
            const int bk   = (ks * 16 + ((lane >> 3) & 1) * 8) * 2;
#pragma unroll
            for (int p = 0; p < 4; p++) {
                uint32_t b[4];
                int n = wn * 64 + p * 16 + bn_l;
                ldsm_x4(b, s0 + BOFF + n * G1_PB + bk);
#pragma unroll
                for (int mt = 0; mt < 2; mt++) {
#pragma unroll
                    for (int j = 0; j < 2; j++)
                        mma_f16(d[mt][2 * p + j], a[mt], b + 2 * j);
                }
            }
        }
    }

    // ---- epilogue: relu(acc + bias) -> fp16 h1
#pragma unroll
    for (int mt = 0; mt < 2; mt++) {
        int row0 = brow + wm * 32 + mt * 16 + (lane >> 2);
#pragma unroll
        for (int nt = 0; nt < 8; nt++) {
            int col = bcol + wn * 64 + nt * 8 + (lane & 3) * 2;
            float b0 = bias[col], b1 = bias[col + 1];
#pragma unroll
            for (int h = 0; h < 2; h++) {
                int r = row0 + h * 8;
                if (r >= M) continue;
                __half2 hv = __floats2half2_rn(fmaxf(d[mt][nt][2 * h + 0] + b0, 0.f),
                                               fmaxf(d[mt][nt][2 * h + 1] + b1, 0.f));
                *(__half2*)(g_h1h + (size_t)r * HID_DIM + col) = hv;
            }
        }
    }
}

// ============ GEMM2 (mma.sync fp16): H0 = h1 @ W2 + b2 -> fp16 ============
#define G2_NKC   (HID_DIM / 64)       // 8
#define G2_P     144
#define G2_AT    (128 * G2_P)         // 18432
#define G2_BT    (64 * G2_P)          // 9216
#define G2_ST    (G2_AT + G2_BT)      // 27648
#define G2_SMEM  (3 * G2_ST)          // 82944

__global__ __launch_bounds__(256, 2) void gemm2_mma_kernel(const float* __restrict__ bias, int M)
{
    extern __shared__ char smem[];
    const int tid  = threadIdx.x;
    const int wid  = tid >> 5, lane = tid & 31;
    const int wm   = wid & 3,  wn   = wid >> 2;      // 4 x 2 warps
    const int brow = blockIdx.x * 128;

    const uint32_t sbase = smem_u32(smem);
    const uint32_t AOFF = 0, BOFF = G2_AT;

    float d[2][4][4];
#pragma unroll
    for (int i = 0; i < 2; i++)
#pragma unroll
        for (int j = 0; j < 4; j++)
#pragma unroll
            for (int k = 0; k < 4; k++) d[i][j][k] = 0.f;

    auto issue_load = [&](int kc, int st) {
        const int k0 = kc * 64;
        const uint32_t s0 = sbase + st * G2_ST;
#pragma unroll
        for (int i = 0; i < 4; i++) {  // A: 1024 segs
            int seg = tid + i * 256;
            int row = seg >> 3, sc = seg & 7;
            uint32_t soff = row * G2_P + sc * 16;
            int ar = brow + row;
            int ok = (ar < M);
            size_t gA = (size_t)(ok ? ar : 0) * HID_DIM + k0 + sc * 8;
            cp_async16(s0 + AOFF + soff, g_h1h + gA, ok ? 16 : 0);
        }
#pragma unroll
        for (int i = 0; i < 2; i++) {  // B: 512 segs
            int seg = tid + i * 256;
            int row = seg >> 3, sc = seg & 7;
            uint32_t soff = row * G2_P + sc * 16;
            size_t gB = (size_t)row * HID_DIM + k0 + sc * 8;
            cp_async16(s0 + BOFF + soff, g_w2t + gB, 16);
        }
        cp_commit();
    };

    issue_load(0, 0);
    issue_load(1, 1);

    for (int kc = 0; kc < G2_NKC; kc++) {
        if (kc == G2_NKC - 1) cp_wait<0>(); else cp_wait<1>();
        __syncthreads();
        if (kc + 2 < G2_NKC) issue_load(kc + 2, (kc + 2) % 3);

        const uint32_t s0 = sbase + (kc % 3) * G2_ST;
#pragma unroll
        for (int ks = 0; ks < 4; ks++) {
            uint32_t a[2][4];
            const int ac = (ks * 16 + (lane >> 4) * 8) * 2;
#pragma unroll
            for (int mt = 0; mt < 2; mt++) {
                int r = wm * 32 + mt * 16 + (lane & 15);
                ldsm_x4(a[mt], s0 + AOFF + r * G2_P + ac);
            }
            const int bn_l = (lane >> 4) * 8 + (lane & 7);
            const int bk   = (ks * 16 + ((lane >> 3) & 1) * 8) * 2;
#pragma unroll
            for (int p = 0; p < 2; p++) {
                uint32_t b[4];
                int n = wn * 32 + p * 16 + bn_l;
                ldsm_x4(b, s0 + BOFF + n * G2_P + bk);
#pragma unroll
                for (int mt = 0; mt < 2; mt++) {
#pragma unroll
                    for (int j = 0; j < 2; j++)
                        mma_f16(d[mt][2 * p + j], a[mt], b + 2 * j);
                }
            }
        }
    }

    // ---- epilogue: + bias, write fp16 H0
#pragma unroll
    for (int mt = 0; mt < 2; mt++) {
        int row0 = brow + wm * 32 + mt * 16 + (lane >> 2);
#pragma unroll
        for (int nt = 0; nt < 4; nt++) {
            int col = wn * 32 + nt * 8 + (lane & 3) * 2;
            float b0 = bias[col], b1 = bias[col + 1];
#pragma unroll
            for (int h = 0; h < 2; h++) {
                int r = row0 + h * 8;
                if (r >= M) continue;
                __half2 hv = __floats2half2_rn(d[mt][nt][2 * h + 0] + b0,
                                               d[mt][nt][2 * h + 1] + b1);
                *(__half2*)(g_Hh + (size_t)r * OUT_DIM + col) = hv;
            }
        }
    }
}

// ---------------- CSR build ----------------
__global__ void zero_deg_kernel(int n)
{
    int i = blockIdx.x * blockDim.x + threadIdx.x;
    if (i == 0) g_bar = 0;             // reset persistent-kernel barrier each call
    if (i < n) g_deg[i] = 0;
}

__global__ void hist_kernel(const int* __restrict__ row, int E)
{
    int e = blockIdx.x * blockDim.x + threadIdx.x;
    if (e < E) atomicAdd(&g_deg[row[e]], 1);
}

__global__ __launch_bounds__(1024) void scan_kernel(int n)
{
    __shared__ int sums[1024];
    int tid = threadIdx.x;
    int per = (n + 1023) >> 10;
    int start = tid * per;
    int end = min(start + per, n);

    int s = 0;
    for (int i = start; i < end; ++i) s += g_deg[i];
    sums[tid] = s;
    __syncthreads();

    for (int off = 1; off < 1024; off <<= 1) {
        int v = 0;
        if (tid >= off) v = sums[tid - off];
        __syncthreads();
        sums[tid] += v;
        __syncthreads();
    }

    int run = sums[tid] - s;
    for (int i = start; i < end; ++i) {
        g_rowptr[i] = run;
        g_cursor[i] = run;
        run += g_deg[i];
    }
    if (tid == 1023) g_rowptr[n] = sums[1023];
}

__global__ void scatter_kernel(const int* __restrict__ row, const int* __restrict__ col,
                               const float* __restrict__ w, int E)
{
    int e = blockIdx.x * blockDim.x + threadIdx.x;
    if (e >= E) return;
    int r = row[e];
    int pos = atomicAdd(&g_cursor[r], 1);
    __half hw = __float2half_rn(w[e]);
    __half2 w2 = __half2half2(hw);
    g_edge[pos] = make_int2(col[e], h22bits(w2));
}

// ---- SpMM row body (proven clamped-tail, MLP-8): per-lane f[8] sub-segment sums ----
__device__ __forceinline__ void spmm_row(
    const __half* __restrict__ hin, int2 (*ebuf)[32], int wslot,
    int lane, int grp, int sub, int s, int e, float* f)
{
#pragma unroll
    for (int k = 0; k < 8; k++) f[k] = 0.f;

    for (int base = s; base < e; base += 32) {
        const int cnt = min(32, e - base);
        if (lane < cnt) ebuf[wslot][lane] = g_edge[base + lane];
        __syncwarp();

        __half2 hacc[4];
#pragma unroll
        for (int k = 0; k < 4; k++) hacc[k] = __float2half2_rn(0.f);

        if (cnt == 32) {
#pragma unroll
            for (int it = 0; it < 8; ++it) {
                int2 ed = ebuf[wslot][it * 4 + grp];
                uint4 v = *(const uint4*)(hin + (size_t)ed.x * 64 + sub * 8);
                __half2 w2 = bits2h2(ed.y);
                hacc[0] = __hfma2(w2, bits2h2((int)v.x), hacc[0]);
                hacc[1] = __hfma2(w2, bits2h2((int)v.y), hacc[1]);
                hacc[2] = __hfma2(w2, bits2h2((int)v.z), hacc[2]);
                hacc[3] = __hfma2(w2, bits2h2((int)v.w), hacc[3]);
            }
        } else {
            const int nit = (cnt + 3) >> 2;
            for (int it = 0; it < nit; ++it) {
                int ei = it * 4 + grp;
                int2 ed = ebuf[wslot][ei < cnt ? ei : 0];
                int wb  = (ei < cnt) ? ed.y : 0;
                uint4 v = *(const uint4*)(hin + (size_t)ed.x * 64 + sub * 8);
                __half2 w2 = bits2h2(wb);
                hacc[0] = __hfma2(w2, bits2h2((int)v.x), hacc[0]);
                hacc[1] = __hfma2(w2, bits2h2((int)v.y), hacc[1]);
                hacc[2] = __hfma2(w2, bits2h2((int)v.z), hacc[2]);
                hacc[3] = __hfma2(w2, bits2h2((int)v.w), hacc[3]);
            }
        }
#pragma unroll
        for (int k = 0; k < 4; k++) {
            float2 t = __half22float2(hacc[k]);
            f[2 * k]     += t.x;
            f[2 * k + 1] += t.y;
        }
        __syncwarp();
    }

#pragma unroll
    for (int k = 0; k < 8; k++) {
        f[k] += __shfl_xor_sync(0xffffffffu, f[k], 8);
        f[k] += __shfl_xor_sync(0xffffffffu, f[k], 16);
    }
}

// ------- Persistent SpMM: all 10 hops in one launch, software grid barrier -------
// Grid = SMs x occupancy (queried at init) -> all blocks resident; barrier is a
// monotone counter (g_bar, zeroed by zero_deg_kernel before ev_join).
// Memory safety: buffer k is written only in phase k and read only in phase k+1;
// no SM ever loads buffer-k lines earlier, so no stale L1 copies can exist.
__global__ __launch_bounds__(256) void spmm_persist_kernel(int n, int nblocks)
{
    __shared__ int2 ebuf[8][32];
    const int wslot = threadIdx.x >> 5;
    const int lane  = threadIdx.x & 31;
    const int grp = lane >> 3;
    const int sub = lane & 7;
    const int warp0 = (blockIdx.x * blockDim.x + threadIdx.x) >> 5;
    const int totalWarps = nblocks * (int)(blockDim.x >> 5);

    for (int hop = 1; hop <= HOPS; ++hop) {
        const __half* __restrict__ hin = g_Hh + (size_t)(hop - 1) * N_NODES * OUT_DIM;
        __half* __restrict__ hout      = g_Hh + (size_t)hop * N_NODES * OUT_DIM;

        for (int r = warp0; r < n; r += totalWarps) {
            float f[8];
            spmm_row(hin, ebuf, wslot, lane, grp, sub, g_rowptr[r], g_rowptr[r + 1], f);
            if (grp == 0) {
                union { __half2 h[4]; uint4 u; } o;
#pragma unroll
                for (int k = 0; k < 4; k++)
                    o.h[k] = __floats2half2_rn(f[2 * k], f[2 * k + 1]);
                *(uint4*)(hout + (size_t)r * 64 + sub * 8) = o.u;
            }
        }

        // ---- grid barrier: release stores, arrive, spin on monotone counter ----
        __syncthreads();
        if (threadIdx.x == 0) {
            __threadfence();
            atomicAdd(&g_bar, 1);
            while (*(volatile int*)&g_bar < nblocks * hop) { }
            __threadfence();
        }
        __syncthreads();
    }
}

// ---------------- Combine: 4 rows/warp, vectorized uint4 loads ----------------
__global__ __launch_bounds__(256) void combine_kernel(
    const float* __restrict__ s, float* __restrict__ out, int n)
{
    const int warp = (blockIdx.x * blockDim.x + threadIdx.x) >> 5;
    const int lane = threadIdx.x & 31;
    const int g   = lane >> 3;
    const int sub = lane & 7;
    int row = warp * 4 + g;
    const bool valid = (row < n);
    if (warp * 4 >= n) return;
    if (!valid) row = n - 1;

    float sv[8];
    *(float4*)(sv)     = *(const float4*)(s + sub * 8);
    *(float4*)(sv + 4) = *(const float4*)(s + sub * 8 + 4);

    float acc[8];
#pragma unroll
    for (int j = 0; j < 8; j++) acc[j] = 0.f;

#pragma unroll
    for (int k = 0; k <= HOPS; k++) {
        const __half* hk = g_Hh + (size_t)k * N_NODES * OUT_DIM + (size_t)row * 64 + sub * 8;
        uint4 v = *(const uint4*)hk;
        float2 f0 = __half22float2(bits2h2((int)v.x));
        float2 f1 = __half22float2(bits2h2((int)v.y));
        float2 f2 = __half22float2(bits2h2((int)v.z));
        float2 f3 = __half22float2(bits2h2((int)v.w));
        float fv[8] = {f0.x, f0.y, f1.x, f1.y, f2.x, f2.y, f3.x, f3.y};

        float d = 0.f;
#pragma unroll
        for (int j = 0; j < 8; j++) d += fv[j] * sv[j];
        d += __shfl_xor_sync(0xffffffffu, d, 1);
        d += __shfl_xor_sync(0xffffffffu, d, 2);
        d += __shfl_xor_sync(0xffffffffu, d, 4);
        float sg = 1.f / (1.f + expf(-d));
#pragma unroll
        for (int j = 0; j < 8; j++) acc[j] += sg * fv[j];
    }
    if (valid) {
        float* dst = out + (size_t)row * 64 + sub * 8;
        *(float4*)(dst)     = *(float4*)(acc);
        *(float4*)(dst + 4) = *(float4*)(acc + 4);
    }
}

// ---------------- launch ----------------
extern "C" void kernel_launch(void* const* d_in, const int* in_sizes, int n_in,
                              void* d_out, int out_size)
{
    const float* x   = (const float*)d_in[0];
    const int*   row = (const int*)  d_in[1];
    const int*   col = (const int*)  d_in[2];
    const float* ew  = (const float*)d_in[3];
    const float* W1  = (const float*)d_in[4];
    const float* b1  = (const float*)d_in[5];
    const float* W2  = (const float*)d_in[6];
    const float* b2  = (const float*)d_in[7];
    const float* s   = (const float*)d_in[8];

    int M = in_sizes[0] / IN_DIM;  // 100000
    int E = in_sizes[1];           // 3300000

    static bool attr_set = false;
    static cudaStream_t s_csr = 0;
    static cudaEvent_t ev_fork = 0, ev_join = 0;
    static int persist_blocks = 148;
    if (!attr_set) {
        cudaFuncSetAttribute(gemm1_mma_kernel,
                             cudaFuncAttributeMaxDynamicSharedMemorySize, G1_SMEM);
        cudaFuncSetAttribute(gemm2_mma_kernel,
                             cudaFuncAttributeMaxDynamicSharedMemorySize, G2_SMEM);
        cudaStreamCreateWithFlags(&s_csr, cudaStreamNonBlocking);
        cudaEventCreateWithFlags(&ev_fork, cudaEventDisableTiming);
        cudaEventCreateWithFlags(&ev_join, cudaEventDisableTiming);
        int nsm = 148, occ = 1;
        cudaDeviceGetAttribute(&nsm, cudaDevAttrMultiProcessorCount, 0);
        cudaOccupancyMaxActiveBlocksPerMultiprocessor(&occ, spmm_persist_kernel, 256, 0);
        if (occ < 1) occ = 1;
        persist_blocks = nsm * occ;   // all blocks resident -> barrier is safe
        attr_set = true;
    }

    // ---- fork: CSR build (also resets g_bar) concurrent with conversions + GEMMs ----
    cudaEventRecord(ev_fork, 0);
    cudaStreamWaitEvent(s_csr, ev_fork, 0);
    zero_deg_kernel<<<(M + 255) / 256, 256, 0, s_csr>>>(M);
    hist_kernel<<<(E + 255) / 256, 256, 0, s_csr>>>(row, E);
    scan_kernel<<<1, 1024, 0, s_csr>>>(M);
    scatter_kernel<<<(E + 255) / 256, 256, 0, s_csr>>>(row, col, ew, E);
    cudaEventRecord(ev_join, s_csr);

    // main stream: weight conversions + GEMMs (x converted in-GEMM)
    conv_w1_kernel<<<(HID_DIM * IN_DIM + 255) / 256, 256>>>(W1);
    conv_w2_kernel<<<(OUT_DIM * HID_DIM + 255) / 256, 256>>>(W2);

    dim3 g1((M + 127) / 128, HID_DIM / 256);
    gemm1_mma_kernel<<<g1, 512, G1_SMEM>>>(x, b1, M);
    gemm2_mma_kernel<<<(M + 127) / 128, 256, G2_SMEM>>>(b2, M);

    // ---- join: hops need both the CSR (+ g_bar reset) and H0 ----
    cudaStreamWaitEvent(0, ev_join, 0);

    // all 10 propagation hops in ONE persistent launch
    spmm_persist_kernel<<<persist_blocks, 256>>>(M, persist_blocks);

    // gated combine (4 rows per warp)
    int comb_warps = (M + 3) / 4;
    combine_kernel<<<(comb_warps * 32 + 255) / 256, 256>>>(s, (float*)d_out, M);
}